// round 8
// baseline (speedup 1.0000x reference)
#include <cuda_runtime.h>
#include <cuda_bf16.h>
#include <cstdint>

#define T_STEPS 512
#define BATCH   64
#define DIN     1024
#define HID     128
#define GATES   512   // 4*HID

// Scratch: x1[t][b][g] = feats @ W_ih1^T + b_ih1 + b_hh1   (64 MB)
__device__ float g_x1[(size_t)T_STEPS * BATCH * GATES];

// ---------------------------------------------------------------------------
// helpers
// ---------------------------------------------------------------------------
__device__ __forceinline__ uint32_t s2u(const void* p){
    uint32_t a;
    asm("{ .reg .u64 t; cvta.to.shared.u64 t, %1; cvt.u32.u64 %0, t; }" : "=r"(a) : "l"(p));
    return a;
}
__device__ __forceinline__ void ldsm4(uint32_t* r, uint32_t addr){
    asm volatile("ldmatrix.sync.aligned.m8n8.x4.shared.b16 {%0,%1,%2,%3}, [%4];"
        : "=r"(r[0]), "=r"(r[1]), "=r"(r[2]), "=r"(r[3]) : "r"(addr));
}
__device__ __forceinline__ void mma16816(float* c, const uint32_t* a, const uint32_t* b){
    asm volatile("mma.sync.aligned.m16n8k16.row.col.f32.bf16.bf16.f32 "
        "{%0,%1,%2,%3}, {%4,%5,%6,%7}, {%8,%9}, {%0,%1,%2,%3};"
        : "+f"(c[0]), "+f"(c[1]), "+f"(c[2]), "+f"(c[3])
        : "r"(a[0]), "r"(a[1]), "r"(a[2]), "r"(a[3]), "r"(b[0]), "r"(b[1]));
}
// hi bf16 pair = truncated top-16 bits of (x,y)
__device__ __forceinline__ uint2 hi_pair(float4 v){
    uint32_t x = __float_as_uint(v.x), y = __float_as_uint(v.y);
    uint32_t z = __float_as_uint(v.z), w = __float_as_uint(v.w);
    uint32_t h0, h1;
    asm("prmt.b32 %0, %1, %2, 0x7632;" : "=r"(h0) : "r"(x), "r"(y));
    asm("prmt.b32 %0, %1, %2, 0x7632;" : "=r"(h1) : "r"(z), "r"(w));
    return make_uint2(h0, h1);
}
// lo residual pair (exact subtract of truncated hi, then rn to bf16)
__device__ __forceinline__ uint2 lo_pair(float4 v){
    float lx = v.x - __uint_as_float(__float_as_uint(v.x) & 0xFFFF0000u);
    float ly = v.y - __uint_as_float(__float_as_uint(v.y) & 0xFFFF0000u);
    float lz = v.z - __uint_as_float(__float_as_uint(v.z) & 0xFFFF0000u);
    float lw = v.w - __uint_as_float(__float_as_uint(v.w) & 0xFFFF0000u);
    uint32_t l0, l1;
    asm("cvt.rn.bf16x2.f32 %0, %1, %2;" : "=r"(l0) : "f"(ly), "f"(lx));
    asm("cvt.rn.bf16x2.f32 %0, %1, %2;" : "=r"(l1) : "f"(lw), "f"(lz));
    return make_uint2(l0, l1);
}
__device__ __forceinline__ unsigned long long fma2(unsigned long long a,
        unsigned long long b, unsigned long long c){
    unsigned long long d;
    asm("fma.rn.f32x2 %0, %1, %2, %3;" : "=l"(d) : "l"(a), "l"(b), "l"(c));
    return d;
}
__device__ __forceinline__ unsigned long long packf2(float x, float y){
    unsigned long long r;
    asm("mov.b64 %0, {%1, %2};" : "=l"(r) : "f"(x), "f"(y));
    return r;
}
__device__ __forceinline__ float hsum2(unsigned long long v){
    return __uint_as_float((uint32_t)v) + __uint_as_float((uint32_t)(v >> 32));
}
__device__ __forceinline__ float sigf(float x){
    return __fdividef(1.0f, 1.0f + __expf(-x));
}
__device__ __forceinline__ float tanhfast(float x){
    return 2.0f * __fdividef(1.0f, 1.0f + __expf(-2.0f * x)) - 1.0f;
}

// ---------------------------------------------------------------------------
// Kernel 1: x1 GEMM via split-bf16 mma.sync (3 passes: hh + lh + hl).
// (unchanged — 263us, protected)
// ---------------------------------------------------------------------------
#define PITCH 80
#define TILE_B (128 * PITCH)      // 10240
#define O_AHI 0
#define O_ALO (1 * TILE_B)
#define O_BHI (2 * TILE_B)
#define O_BLO (3 * TILE_B)
#define BUFB  (4 * TILE_B)        // 40960
#define GSMEM (2 * BUFB)          // 81920

__global__ __launch_bounds__(256, 1) void x1_gemm_hmma(
    const float* __restrict__ A,
    const float* __restrict__ W,
    const float* __restrict__ bih,
    const float* __restrict__ bhh)
{
    extern __shared__ __align__(128) char smg[];
    __shared__ float biasS[128];
    const int tid  = threadIdx.x;
    const int lane = tid & 31, wid = tid >> 5;
    const int wm = wid & 3, wn = wid >> 2;
    const int m0 = blockIdx.y << 7, n0 = blockIdx.x << 7;

    if (tid < 128) biasS[tid] = bih[n0 + tid] + bhh[n0 + tid];

    const int lrow = tid >> 3;
    const int lc4  = tid & 7;
    const float* Abase = A + (size_t)(m0 + lrow) * DIN + lc4 * 4;
    const float* Wbase = W + (size_t)(n0 + lrow) * DIN + lc4 * 4;
    const int soff = lrow * PITCH + lc4 * 8;

    const uint32_t sbase = s2u(smg);
    const uint32_t a_off = (uint32_t)((wm * 32 + (lane & 15)) * PITCH + (lane >> 4) * 16);
    const uint32_t b_off = (uint32_t)((wn * 64 + (lane & 7) + 8 * (lane >> 4)) * PITCH
                                      + ((lane >> 3) & 1) * 16);

    float c[2][8][4];
    #pragma unroll
    for (int i = 0; i < 2; i++)
        #pragma unroll
        for (int j = 0; j < 8; j++)
            #pragma unroll
            for (int k = 0; k < 4; k++) c[i][j][k] = 0.f;

    float4 ra[4], rw[4];
    #pragma unroll
    for (int i = 0; i < 4; i++){
        ra[i] = *(const float4*)(Abase + (size_t)(32 * i) * DIN);
        rw[i] = *(const float4*)(Wbase + (size_t)(32 * i) * DIN);
    }
    #pragma unroll
    for (int i = 0; i < 4; i++){
        int off = soff + i * 32 * PITCH;
        *(uint2*)(smg + O_AHI + off) = hi_pair(ra[i]);
        *(uint2*)(smg + O_ALO + off) = lo_pair(ra[i]);
        *(uint2*)(smg + O_BHI + off) = hi_pair(rw[i]);
        *(uint2*)(smg + O_BLO + off) = lo_pair(rw[i]);
    }
    __syncthreads();

    for (int ci = 0; ci < 32; ci++){
        const uint32_t buf = sbase + (uint32_t)(ci & 1) * BUFB;
        if (ci < 31){
            #pragma unroll
            for (int i = 0; i < 4; i++){
                ra[i] = *(const float4*)(Abase + (size_t)(32 * i) * DIN + (ci + 1) * 32);
                rw[i] = *(const float4*)(Wbase + (size_t)(32 * i) * DIN + (ci + 1) * 32);
            }
        }
        #pragma unroll
        for (int kk = 0; kk < 2; kk++){
            uint32_t ah0[4], ah1[4], al0[4], al1[4], bh[4][4], bl[4][4];
            const uint32_t ka = a_off + kk * 32;
            const uint32_t kb = b_off + kk * 32;
            ldsm4(ah0, buf + O_AHI + ka);
            ldsm4(ah1, buf + O_AHI + ka + 16 * PITCH);
            ldsm4(al0, buf + O_ALO + ka);
            ldsm4(al1, buf + O_ALO + ka + 16 * PITCH);
            #pragma unroll
            for (int q2 = 0; q2 < 4; q2++){
                ldsm4(bh[q2], buf + O_BHI + kb + q2 * 16 * PITCH);
                ldsm4(bl[q2], buf + O_BLO + kb + q2 * 16 * PITCH);
            }
            #pragma unroll
            for (int nt = 0; nt < 8; nt++){
                const uint32_t* bhp = &bh[nt >> 1][(nt & 1) * 2];
                const uint32_t* blp = &bl[nt >> 1][(nt & 1) * 2];
                mma16816(c[0][nt], ah0, bhp);
                mma16816(c[1][nt], ah1, bhp);
                mma16816(c[0][nt], al0, bhp);
                mma16816(c[1][nt], al1, bhp);
                mma16816(c[0][nt], ah0, blp);
                mma16816(c[1][nt], ah1, blp);
            }
        }
        if (ci < 31){
            char* b = smg + ((ci + 1) & 1) * BUFB;
            #pragma unroll
            for (int i = 0; i < 4; i++){
                int off = soff + i * 32 * PITCH;
                *(uint2*)(b + O_AHI + off) = hi_pair(ra[i]);
                *(uint2*)(b + O_ALO + off) = lo_pair(ra[i]);
                *(uint2*)(b + O_BHI + off) = hi_pair(rw[i]);
                *(uint2*)(b + O_BLO + off) = lo_pair(rw[i]);
            }
        }
        __syncthreads();
    }

    const int gr = lane >> 2;
    const int gc = (lane & 3) * 2;
    #pragma unroll
    for (int mt = 0; mt < 2; mt++){
        #pragma unroll
        for (int nt = 0; nt < 8; nt++){
            const int n = wn * 64 + nt * 8 + gc;
            const float b0 = biasS[n], b1 = biasS[n + 1];
            #pragma unroll
            for (int rr = 0; rr < 2; rr++){
                const int m = m0 + wm * 32 + mt * 16 + gr + rr * 8;
                const int bb = m >> 9;
                const int tt = m & 511;
                float2 o = make_float2(c[mt][nt][rr * 2 + 0] + b0,
                                       c[mt][nt][rr * 2 + 1] + b1);
                *(float2*)(g_x1 + ((size_t)tt * BATCH + bb) * GATES + n0 + n) = o;
            }
        }
    }
}

// ---------------------------------------------------------------------------
// Kernel 2: recurrence. 32 clusters x 4 CTAs, 2 batches/cluster.
// CHANGE vs round 7: w3 (Whh2 slice) moved from registers to shared memory
// (layout w3s[k4][tid] = 16B per entry -> warp LDS.128 is 512B contiguous,
// conflict-free). Frees 64 regs -> eliminates local-memory spills of the
// weight arrays (the L1=41.5% phantom traffic).
// ---------------------------------------------------------------------------
__device__ __forceinline__ void bcast4(const float* addr, float v){
    uint32_t la = (uint32_t)__cvta_generic_to_shared(addr);
    #pragma unroll
    for (int pr = 0; pr < 4; pr++){
        uint32_t raddr;
        asm volatile("mapa.shared::cluster.u32 %0, %1, %2;" : "=r"(raddr) : "r"(la), "r"(pr));
        asm volatile("st.shared::cluster.f32 [%0], %1;" :: "r"(raddr), "f"(v) : "memory");
    }
}
__device__ __forceinline__ void arrive4(uint32_t la){
    #pragma unroll
    for (int pr = 0; pr < 4; pr++){
        uint32_t raddr;
        asm volatile("mapa.shared::cluster.u32 %0, %1, %2;" : "=r"(raddr) : "r"(la), "r"(pr));
        asm volatile("mbarrier.arrive.shared::cluster.b64 _, [%0];" :: "r"(raddr) : "memory");
    }
}
__device__ __forceinline__ void mbar_wait_c(uint32_t mb, uint32_t parity){
    asm volatile(
        "{\n\t.reg .pred P;\n\t"
        "WL_%=:\n\t"
        "mbarrier.try_wait.parity.acquire.cluster.shared::cta.b64 P, [%0], %1;\n\t"
        "@!P bra WL_%=;\n\t"
        "}\n" :: "r"(mb), "r"(parity) : "memory");
}

#define RSMEM 65536   // dynamic: w3s[16][256] ulonglong2

__global__ void __cluster_dims__(4,1,1) __launch_bounds__(256, 1)
lstm_rec_kernel(const float* __restrict__ Whh1,
                const float* __restrict__ Wih2,
                const float* __restrict__ Whh2,
                const float* __restrict__ bih2,
                const float* __restrict__ bhh2,
                float* __restrict__ out)
{
    extern __shared__ __align__(16) ulonglong2 w3s[];   // [k4][tid] : 16 x 256
    __shared__ __align__(16) float h1s[2][2][HID];
    __shared__ __align__(16) float h2s[2][2][HID];
    __shared__ __align__(8) unsigned long long mbar;

    const int tid  = threadIdx.x;
    const int w    = tid >> 5;
    const int lane = tid & 31;
    const int half = lane >> 4;         // k-half
    const int u    = lane & 15;
    const int g    = u >> 2;            // gate 0..3
    const int jo   = u & 3;
    const int jj   = w * 4 + jo;        // j within this CTA's 32-slice
    uint32_t rank;
    asm("mov.u32 %0, %%cluster_ctarank;" : "=r"(rank));
    const int b0   = (blockIdx.x >> 2) * 2;
    const int grow = g * 128 + (int)rank * 32 + jj;
    const uint32_t mba = (uint32_t)__cvta_generic_to_shared(&mbar);

    // register-resident packed weights for Whh1 and Wih2; Whh2 -> smem
    unsigned long long w1p[32], w2p[32];
    {
        const float4* p1 = (const float4*)(Whh1 + (size_t)grow * HID + half * 64);
        const float4* p2 = (const float4*)(Wih2 + (size_t)grow * HID + half * 64);
        const float4* p3 = (const float4*)(Whh2 + (size_t)grow * HID + half * 64);
        #pragma unroll
        for (int k = 0; k < 16; k++){
            float4 v1 = p1[k], v2 = p2[k], v3 = p3[k];
            w1p[2*k]   = packf2(v1.x, v1.y);  w1p[2*k+1] = packf2(v1.z, v1.w);
            w2p[2*k]   = packf2(v2.x, v2.y);  w2p[2*k+1] = packf2(v2.z, v2.w);
            ulonglong2 e;
            e.x = packf2(v3.x, v3.y);  e.y = packf2(v3.z, v3.w);
            w3s[k * 256 + tid] = e;
        }
    }
    const float b2v = bih2[grow] + bhh2[grow];

    for (int i = tid; i < 2*2*HID; i += 256){
        (&h1s[0][0][0])[i] = 0.f;
        (&h2s[0][0][0])[i] = 0.f;
    }
    if (tid == 0){
        asm volatile("mbarrier.init.shared.b64 [%0], %1;" :: "r"(mba), "r"(32u) : "memory");
    }
    __syncthreads();
    asm volatile("barrier.cluster.arrive.aligned;" ::: "memory");
    asm volatile("barrier.cluster.wait.aligned;"   ::: "memory");

    // Prologue: layer1(t=0) from x only. Gate-unit lanes 0-7 own c1, 8-15 own c2.
    float cst = 0.f;
    if (lane < 8){
        const int b = (lane >> 2) & 1;
        const float* xp = g_x1 + ((size_t)0 * BATCH + b0 + b) * GATES + (int)rank * 32 + jj;
        float p0 = xp[0], p2 = xp[256], p3 = xp[384];
        cst = sigf(p0) * tanhfast(p2);
        float h = sigf(p3) * tanhfast(cst);
        bcast4(&h1s[0][b][(int)rank * 32 + jj], h);
    }
    __syncwarp();
    if (lane == 0) arrive4(mba);
    float xv0 = 0.f, xv1 = 0.f;
    if (half == 0){
        const float* xp = g_x1 + ((size_t)1 * BATCH + b0) * GATES + grow;
        xv0 = xp[0];
        xv1 = xp[GATES];
    }
    mbar_wait_c(mba, 0);

    int cur = 0;
    for (int t = 0; t < T_STEPS; t++){
        const int nxt = cur ^ 1;

        // packed dot products for layer1(t+1) and layer2(t)
        const float4* A0 = (const float4*)&h1s[cur][0][half * 64];
        const float4* A1 = (const float4*)&h1s[cur][1][half * 64];
        const float4* D0 = (const float4*)&h2s[cur][0][half * 64];
        const float4* D1 = (const float4*)&h2s[cur][1][half * 64];
        unsigned long long q10 = 0ull, q11 = 0ull;
        unsigned long long q20 = 0ull, q21 = 0ull, r20 = 0ull, r21 = 0ull;
        #pragma unroll
        for (int k4 = 0; k4 < 16; k4++){
            float4 a0 = A0[k4], a1 = A1[k4], d0 = D0[k4], d1 = D1[k4];
            ulonglong2 w3v = w3s[k4 * 256 + tid];
            unsigned long long a0p = packf2(a0.x, a0.y), a0q = packf2(a0.z, a0.w);
            unsigned long long a1p = packf2(a1.x, a1.y), a1q = packf2(a1.z, a1.w);
            unsigned long long d0p = packf2(d0.x, d0.y), d0q = packf2(d0.z, d0.w);
            unsigned long long d1p = packf2(d1.x, d1.y), d1q = packf2(d1.z, d1.w);
            q10 = fma2(w1p[2*k4], a0p, q10);  q10 = fma2(w1p[2*k4+1], a0q, q10);
            q11 = fma2(w1p[2*k4], a1p, q11);  q11 = fma2(w1p[2*k4+1], a1q, q11);
            q20 = fma2(w2p[2*k4], a0p, q20);  q20 = fma2(w2p[2*k4+1], a0q, q20);
            q21 = fma2(w2p[2*k4], a1p, q21);  q21 = fma2(w2p[2*k4+1], a1q, q21);
            r20 = fma2(w3v.x, d0p, r20);      r20 = fma2(w3v.y, d0q, r20);
            r21 = fma2(w3v.x, d1p, r21);      r21 = fma2(w3v.y, d1q, r21);
        }
        float s10 = hsum2(q10) + xv0;
        float s11 = hsum2(q11) + xv1;
        float s20 = hsum2(q20) + hsum2(r20) + (half ? 0.f : b2v);
        float s21 = hsum2(q21) + hsum2(r21) + (half ? 0.f : b2v);
        s10 += __shfl_xor_sync(0xFFFFFFFFu, s10, 16);
        s11 += __shfl_xor_sync(0xFFFFFFFFu, s11, 16);
        s20 += __shfl_xor_sync(0xFFFFFFFFu, s20, 16);
        s21 += __shfl_xor_sync(0xFFFFFFFFu, s21, 16);

        // redistribute: target lane<16 gathers all 4 gates of its unit
        float t10[4], t11[4], t20[4], t21[4];
        #pragma unroll
        for (int gg = 0; gg < 4; gg++){
            int src = gg * 4 + (lane & 3);
            t10[gg] = __shfl_sync(0xFFFFFFFFu, s10, src);
            t11[gg] = __shfl_sync(0xFFFFFFFFu, s11, src);
            t20[gg] = __shfl_sync(0xFFFFFFFFu, s20, src);
            t21[gg] = __shfl_sync(0xFFFFFFFFu, s21, src);
        }

        float outv = 0.f;
        if (lane < 16){
            const int L = lane >> 3;             // 0: layer1(t+1), 1: layer2(t)
            const int b = (lane >> 2) & 1;
            float p0, p1, p2, p3;
            if (L == 0){
                p0 = b ? t11[0] : t10[0];  p1 = b ? t11[1] : t10[1];
                p2 = b ? t11[2] : t10[2];  p3 = b ? t11[3] : t10[3];
            } else {
                p0 = b ? t21[0] : t20[0];  p1 = b ? t21[1] : t20[1];
                p2 = b ? t21[2] : t20[2];  p3 = b ? t21[3] : t20[3];
            }
            if (L == 1 || t < T_STEPS - 1){
                float cn = sigf(p1) * cst + sigf(p0) * tanhfast(p2);
                cst = cn;
                float h = sigf(p3) * tanhfast(cn);
                if (L == 0){
                    bcast4(&h1s[nxt][b][(int)rank * 32 + jj], h);
                } else {
                    bcast4(&h2s[nxt][b][(int)rank * 32 + jj], h);
                    outv = h;
                }
            }
        }
        __syncwarp();
        if (lane == 0) arrive4(mba);

        // hidden in the arrive->wait window: output store + x prefetch (t+2)
        if (lane >= 8 && lane < 16)
            out[((size_t)(b0 + ((lane >> 2) & 1)) * T_STEPS + t) * HID + (int)rank * 32 + jj] = outv;
        float nx0 = 0.f, nx1 = 0.f;
        if (half == 0 && t < T_STEPS - 2){
            const float* xp = g_x1 + ((size_t)(t + 2) * BATCH + b0) * GATES + grow;
            nx0 = xp[0];
            nx1 = xp[GATES];
        }

        mbar_wait_c(mba, (t + 1) & 1);
        xv0 = nx0; xv1 = nx1;
        cur = nxt;
    }
}

// ---------------------------------------------------------------------------
extern "C" void kernel_launch(void* const* d_in, const int* in_sizes, int n_in,
                              void* d_out, int out_size)
{
    (void)in_sizes; (void)n_in; (void)out_size;
    const float* feats = (const float*)d_in[0];
    const float* W_ih1 = (const float*)d_in[1];
    const float* W_hh1 = (const float*)d_in[2];
    const float* b_ih1 = (const float*)d_in[3];
    const float* b_hh1 = (const float*)d_in[4];
    const float* W_ih2 = (const float*)d_in[5];
    const float* W_hh2 = (const float*)d_in[6];
    const float* b_ih2 = (const float*)d_in[7];
    const float* b_hh2 = (const float*)d_in[8];
    float* out = (float*)d_out;

    cudaFuncSetAttribute(x1_gemm_hmma, cudaFuncAttributeMaxDynamicSharedMemorySize, GSMEM);
    cudaFuncSetAttribute(lstm_rec_kernel, cudaFuncAttributeMaxDynamicSharedMemorySize, RSMEM);

    dim3 g1(GATES / 128, (BATCH * T_STEPS) / 128);   // (4, 256)
    x1_gemm_hmma<<<g1, 256, GSMEM>>>(feats, W_ih1, b_ih1, b_hh1);

    lstm_rec_kernel<<<128, 256, RSMEM>>>(W_hh1, W_ih2, W_hh2, b_ih2, b_hh2, out);
}

// round 12
// speedup vs baseline: 1.6272x; 1.6272x over previous
#include <cuda_runtime.h>
#include <cuda_bf16.h>
#include <cstdint>

#define T_STEPS 512
#define BATCH   64
#define DIN     1024
#define HID     128
#define GATES   512   // 4*HID

// Scratch: x1[t][b][g] = feats @ W_ih1^T + b_ih1 + b_hh1   (64 MB)
__device__ float g_x1[(size_t)T_STEPS * BATCH * GATES];

// ---------------------------------------------------------------------------
// helpers
// ---------------------------------------------------------------------------
__device__ __forceinline__ uint32_t s2u(const void* p){
    uint32_t a;
    asm("{ .reg .u64 t; cvta.to.shared.u64 t, %1; cvt.u32.u64 %0, t; }" : "=r"(a) : "l"(p));
    return a;
}
__device__ __forceinline__ void ldsm4(uint32_t* r, uint32_t addr){
    asm volatile("ldmatrix.sync.aligned.m8n8.x4.shared.b16 {%0,%1,%2,%3}, [%4];"
        : "=r"(r[0]), "=r"(r[1]), "=r"(r[2]), "=r"(r[3]) : "r"(addr));
}
__device__ __forceinline__ void mma16816(float* c, const uint32_t* a, const uint32_t* b){
    asm volatile("mma.sync.aligned.m16n8k16.row.col.f32.bf16.bf16.f32 "
        "{%0,%1,%2,%3}, {%4,%5,%6,%7}, {%8,%9}, {%0,%1,%2,%3};"
        : "+f"(c[0]), "+f"(c[1]), "+f"(c[2]), "+f"(c[3])
        : "r"(a[0]), "r"(a[1]), "r"(a[2]), "r"(a[3]), "r"(b[0]), "r"(b[1]));
}
// hi bf16 pair = truncated top-16 bits of (x,y)
__device__ __forceinline__ uint2 hi_pair(float4 v){
    uint32_t x = __float_as_uint(v.x), y = __float_as_uint(v.y);
    uint32_t z = __float_as_uint(v.z), w = __float_as_uint(v.w);
    uint32_t h0, h1;
    asm("prmt.b32 %0, %1, %2, 0x7632;" : "=r"(h0) : "r"(x), "r"(y));
    asm("prmt.b32 %0, %1, %2, 0x7632;" : "=r"(h1) : "r"(z), "r"(w));
    return make_uint2(h0, h1);
}
// lo residual pair (exact subtract of truncated hi, then rn to bf16)
__device__ __forceinline__ uint2 lo_pair(float4 v){
    float lx = v.x - __uint_as_float(__float_as_uint(v.x) & 0xFFFF0000u);
    float ly = v.y - __uint_as_float(__float_as_uint(v.y) & 0xFFFF0000u);
    float lz = v.z - __uint_as_float(__float_as_uint(v.z) & 0xFFFF0000u);
    float lw = v.w - __uint_as_float(__float_as_uint(v.w) & 0xFFFF0000u);
    uint32_t l0, l1;
    asm("cvt.rn.bf16x2.f32 %0, %1, %2;" : "=r"(l0) : "f"(ly), "f"(lx));
    asm("cvt.rn.bf16x2.f32 %0, %1, %2;" : "=r"(l1) : "f"(lw), "f"(lz));
    return make_uint2(l0, l1);
}
__device__ __forceinline__ unsigned long long fma2(unsigned long long a,
        unsigned long long b, unsigned long long c){
    unsigned long long d;
    asm("fma.rn.f32x2 %0, %1, %2, %3;" : "=l"(d) : "l"(a), "l"(b), "l"(c));
    return d;
}
__device__ __forceinline__ unsigned long long packf2(float x, float y){
    unsigned long long r;
    asm("mov.b64 %0, {%1, %2};" : "=l"(r) : "f"(x), "f"(y));
    return r;
}
__device__ __forceinline__ float hsum2(unsigned long long v){
    return __uint_as_float((uint32_t)v) + __uint_as_float((uint32_t)(v >> 32));
}
__device__ __forceinline__ float sigf(float x){
    return __fdividef(1.0f, 1.0f + __expf(-x));
}
__device__ __forceinline__ float tanhfast(float x){
    return 2.0f * __fdividef(1.0f, 1.0f + __expf(-2.0f * x)) - 1.0f;
}

// ---------------------------------------------------------------------------
// Kernel 1: x1 GEMM via split-bf16 mma.sync (3 passes: hh + lh + hl).
// (unchanged — 263us, protected)
// ---------------------------------------------------------------------------
#define PITCH 80
#define TILE_B (128 * PITCH)      // 10240
#define O_AHI 0
#define O_ALO (1 * TILE_B)
#define O_BHI (2 * TILE_B)
#define O_BLO (3 * TILE_B)
#define BUFB  (4 * TILE_B)        // 40960
#define GSMEM (2 * BUFB)          // 81920

__global__ __launch_bounds__(256, 1) void x1_gemm_hmma(
    const float* __restrict__ A,
    const float* __restrict__ W,
    const float* __restrict__ bih,
    const float* __restrict__ bhh)
{
    extern __shared__ __align__(128) char smg[];
    __shared__ float biasS[128];
    const int tid  = threadIdx.x;
    const int lane = tid & 31, wid = tid >> 5;
    const int wm = wid & 3, wn = wid >> 2;
    const int m0 = blockIdx.y << 7, n0 = blockIdx.x << 7;

    if (tid < 128) biasS[tid] = bih[n0 + tid] + bhh[n0 + tid];

    const int lrow = tid >> 3;
    const int lc4  = tid & 7;
    const float* Abase = A + (size_t)(m0 + lrow) * DIN + lc4 * 4;
    const float* Wbase = W + (size_t)(n0 + lrow) * DIN + lc4 * 4;
    const int soff = lrow * PITCH + lc4 * 8;

    const uint32_t sbase = s2u(smg);
    const uint32_t a_off = (uint32_t)((wm * 32 + (lane & 15)) * PITCH + (lane >> 4) * 16);
    const uint32_t b_off = (uint32_t)((wn * 64 + (lane & 7) + 8 * (lane >> 4)) * PITCH
                                      + ((lane >> 3) & 1) * 16);

    float c[2][8][4];
    #pragma unroll
    for (int i = 0; i < 2; i++)
        #pragma unroll
        for (int j = 0; j < 8; j++)
            #pragma unroll
            for (int k = 0; k < 4; k++) c[i][j][k] = 0.f;

    float4 ra[4], rw[4];
    #pragma unroll
    for (int i = 0; i < 4; i++){
        ra[i] = *(const float4*)(Abase + (size_t)(32 * i) * DIN);
        rw[i] = *(const float4*)(Wbase + (size_t)(32 * i) * DIN);
    }
    #pragma unroll
    for (int i = 0; i < 4; i++){
        int off = soff + i * 32 * PITCH;
        *(uint2*)(smg + O_AHI + off) = hi_pair(ra[i]);
        *(uint2*)(smg + O_ALO + off) = lo_pair(ra[i]);
        *(uint2*)(smg + O_BHI + off) = hi_pair(rw[i]);
        *(uint2*)(smg + O_BLO + off) = lo_pair(rw[i]);
    }
    __syncthreads();

    for (int ci = 0; ci < 32; ci++){
        const uint32_t buf = sbase + (uint32_t)(ci & 1) * BUFB;
        if (ci < 31){
            #pragma unroll
            for (int i = 0; i < 4; i++){
                ra[i] = *(const float4*)(Abase + (size_t)(32 * i) * DIN + (ci + 1) * 32);
                rw[i] = *(const float4*)(Wbase + (size_t)(32 * i) * DIN + (ci + 1) * 32);
            }
        }
        #pragma unroll
        for (int kk = 0; kk < 2; kk++){
            uint32_t ah0[4], ah1[4], al0[4], al1[4], bh[4][4], bl[4][4];
            const uint32_t ka = a_off + kk * 32;
            const uint32_t kb = b_off + kk * 32;
            ldsm4(ah0, buf + O_AHI + ka);
            ldsm4(ah1, buf + O_AHI + ka + 16 * PITCH);
            ldsm4(al0, buf + O_ALO + ka);
            ldsm4(al1, buf + O_ALO + ka + 16 * PITCH);
            #pragma unroll
            for (int q2 = 0; q2 < 4; q2++){
                ldsm4(bh[q2], buf + O_BHI + kb + q2 * 16 * PITCH);
                ldsm4(bl[q2], buf + O_BLO + kb + q2 * 16 * PITCH);
            }
            #pragma unroll
            for (int nt = 0; nt < 8; nt++){
                const uint32_t* bhp = &bh[nt >> 1][(nt & 1) * 2];
                const uint32_t* blp = &bl[nt >> 1][(nt & 1) * 2];
                mma16816(c[0][nt], ah0, bhp);
                mma16816(c[1][nt], ah1, bhp);
                mma16816(c[0][nt], al0, bhp);
                mma16816(c[1][nt], al1, bhp);
                mma16816(c[0][nt], ah0, blp);
                mma16816(c[1][nt], ah1, blp);
            }
        }
        if (ci < 31){
            char* b = smg + ((ci + 1) & 1) * BUFB;
            #pragma unroll
            for (int i = 0; i < 4; i++){
                int off = soff + i * 32 * PITCH;
                *(uint2*)(b + O_AHI + off) = hi_pair(ra[i]);
                *(uint2*)(b + O_ALO + off) = lo_pair(ra[i]);
                *(uint2*)(b + O_BHI + off) = hi_pair(rw[i]);
                *(uint2*)(b + O_BLO + off) = lo_pair(rw[i]);
            }
        }
        __syncthreads();
    }

    const int gr = lane >> 2;
    const int gc = (lane & 3) * 2;
    #pragma unroll
    for (int mt = 0; mt < 2; mt++){
        #pragma unroll
        for (int nt = 0; nt < 8; nt++){
            const int n = wn * 64 + nt * 8 + gc;
            const float b0 = biasS[n], b1 = biasS[n + 1];
            #pragma unroll
            for (int rr = 0; rr < 2; rr++){
                const int m = m0 + wm * 32 + mt * 16 + gr + rr * 8;
                const int bb = m >> 9;
                const int tt = m & 511;
                float2 o = make_float2(c[mt][nt][rr * 2 + 0] + b0,
                                       c[mt][nt][rr * 2 + 1] + b1);
                *(float2*)(g_x1 + ((size_t)tt * BATCH + bb) * GATES + n0 + n) = o;
            }
        }
    }
}

// ---------------------------------------------------------------------------
// Kernel 2: recurrence. 32 clusters x 4 CTAs, 2 batches/cluster.
// All 3 weight matrices in registers; h vectors loaded as ulonglong2
// (LDS.128 -> two ready f32x2 operands, zero packing movs). In-warp shuffle
// reduction + DSMEM mbarrier sync.
// ---------------------------------------------------------------------------
__device__ __forceinline__ void bcast4(const float* addr, float v){
    uint32_t la = (uint32_t)__cvta_generic_to_shared(addr);
    #pragma unroll
    for (int pr = 0; pr < 4; pr++){
        uint32_t raddr;
        asm volatile("mapa.shared::cluster.u32 %0, %1, %2;" : "=r"(raddr) : "r"(la), "r"(pr));
        asm volatile("st.shared::cluster.f32 [%0], %1;" :: "r"(raddr), "f"(v) : "memory");
    }
}
__device__ __forceinline__ void arrive4(uint32_t la){
    #pragma unroll
    for (int pr = 0; pr < 4; pr++){
        uint32_t raddr;
        asm volatile("mapa.shared::cluster.u32 %0, %1, %2;" : "=r"(raddr) : "r"(la), "r"(pr));
        asm volatile("mbarrier.arrive.shared::cluster.b64 _, [%0];" :: "r"(raddr) : "memory");
    }
}
__device__ __forceinline__ void mbar_wait_c(uint32_t mb, uint32_t parity){
    asm volatile(
        "{\n\t.reg .pred P;\n\t"
        "WL_%=:\n\t"
        "mbarrier.try_wait.parity.acquire.cluster.shared::cta.b64 P, [%0], %1;\n\t"
        "@!P bra WL_%=;\n\t"
        "}\n" :: "r"(mb), "r"(parity) : "memory");
}

__global__ void __cluster_dims__(4,1,1) __launch_bounds__(256, 1)
lstm_rec_kernel(const float* __restrict__ Whh1,
                const float* __restrict__ Wih2,
                const float* __restrict__ Whh2,
                const float* __restrict__ bih2,
                const float* __restrict__ bhh2,
                float* __restrict__ out)
{
    __shared__ __align__(16) float h1s[2][2][HID];
    __shared__ __align__(16) float h2s[2][2][HID];
    __shared__ __align__(8) unsigned long long mbar;

    const int tid  = threadIdx.x;
    const int w    = tid >> 5;
    const int lane = tid & 31;
    const int half = lane >> 4;         // k-half
    const int u    = lane & 15;
    const int g    = u >> 2;            // gate 0..3
    const int jo   = u & 3;
    const int jj   = w * 4 + jo;        // j within this CTA's 32-slice
    uint32_t rank;
    asm("mov.u32 %0, %%cluster_ctarank;" : "=r"(rank));
    const int b0   = (blockIdx.x >> 2) * 2;
    const int grow = g * 128 + (int)rank * 32 + jj;
    const uint32_t mba = (uint32_t)__cvta_generic_to_shared(&mbar);

    // register-resident packed weight slices (96 b64 = 192 regs)
    unsigned long long w1p[32], w2p[32], w3p[32];
    {
        const float4* p1 = (const float4*)(Whh1 + (size_t)grow * HID + half * 64);
        const float4* p2 = (const float4*)(Wih2 + (size_t)grow * HID + half * 64);
        const float4* p3 = (const float4*)(Whh2 + (size_t)grow * HID + half * 64);
        #pragma unroll
        for (int k = 0; k < 16; k++){
            float4 v1 = p1[k], v2 = p2[k], v3 = p3[k];
            w1p[2*k]   = packf2(v1.x, v1.y);  w1p[2*k+1] = packf2(v1.z, v1.w);
            w2p[2*k]   = packf2(v2.x, v2.y);  w2p[2*k+1] = packf2(v2.z, v2.w);
            w3p[2*k]   = packf2(v3.x, v3.y);  w3p[2*k+1] = packf2(v3.z, v3.w);
        }
    }
    const float b2v = bih2[grow] + bhh2[grow];

    for (int i = tid; i < 2*2*HID; i += 256){
        (&h1s[0][0][0])[i] = 0.f;
        (&h2s[0][0][0])[i] = 0.f;
    }
    if (tid == 0){
        asm volatile("mbarrier.init.shared.b64 [%0], %1;" :: "r"(mba), "r"(32u) : "memory");
    }
    __syncthreads();
    asm volatile("barrier.cluster.arrive.aligned;" ::: "memory");
    asm volatile("barrier.cluster.wait.aligned;"   ::: "memory");

    // Prologue: layer1(t=0) from x only. Gate-unit lanes 0-7 own c1, 8-15 own c2.
    float cst = 0.f;
    if (lane < 8){
        const int b = (lane >> 2) & 1;
        const float* xp = g_x1 + ((size_t)0 * BATCH + b0 + b) * GATES + (int)rank * 32 + jj;
        float p0 = xp[0], p2 = xp[256], p3 = xp[384];
        cst = sigf(p0) * tanhfast(p2);
        float h = sigf(p3) * tanhfast(cst);
        bcast4(&h1s[0][b][(int)rank * 32 + jj], h);
    }
    __syncwarp();
    if (lane == 0) arrive4(mba);
    float xv0 = 0.f, xv1 = 0.f;
    if (half == 0){
        const float* xp = g_x1 + ((size_t)1 * BATCH + b0) * GATES + grow;
        xv0 = xp[0];
        xv1 = xp[GATES];
    }
    mbar_wait_c(mba, 0);

    int cur = 0;
    for (int t = 0; t < T_STEPS; t++){
        const int nxt = cur ^ 1;

        // packed dot products: LDS.128 yields two f32x2 operands directly
        const ulonglong2* A0 = (const ulonglong2*)&h1s[cur][0][half * 64];
        const ulonglong2* A1 = (const ulonglong2*)&h1s[cur][1][half * 64];
        const ulonglong2* D0 = (const ulonglong2*)&h2s[cur][0][half * 64];
        const ulonglong2* D1 = (const ulonglong2*)&h2s[cur][1][half * 64];
        unsigned long long q10 = 0ull, q11 = 0ull;
        unsigned long long q20 = 0ull, q21 = 0ull, r20 = 0ull, r21 = 0ull;
        #pragma unroll
        for (int k4 = 0; k4 < 16; k4++){
            ulonglong2 a0 = A0[k4], a1 = A1[k4], d0 = D0[k4], d1 = D1[k4];
            q10 = fma2(w1p[2*k4], a0.x, q10);  q10 = fma2(w1p[2*k4+1], a0.y, q10);
            q11 = fma2(w1p[2*k4], a1.x, q11);  q11 = fma2(w1p[2*k4+1], a1.y, q11);
            q20 = fma2(w2p[2*k4], a0.x, q20);  q20 = fma2(w2p[2*k4+1], a0.y, q20);
            q21 = fma2(w2p[2*k4], a1.x, q21);  q21 = fma2(w2p[2*k4+1], a1.y, q21);
            r20 = fma2(w3p[2*k4], d0.x, r20);  r20 = fma2(w3p[2*k4+1], d0.y, r20);
            r21 = fma2(w3p[2*k4], d1.x, r21);  r21 = fma2(w3p[2*k4+1], d1.y, r21);
        }
        float s10 = hsum2(q10) + xv0;
        float s11 = hsum2(q11) + xv1;
        float s20 = hsum2(q20) + hsum2(r20) + (half ? 0.f : b2v);
        float s21 = hsum2(q21) + hsum2(r21) + (half ? 0.f : b2v);
        s10 += __shfl_xor_sync(0xFFFFFFFFu, s10, 16);
        s11 += __shfl_xor_sync(0xFFFFFFFFu, s11, 16);
        s20 += __shfl_xor_sync(0xFFFFFFFFu, s20, 16);
        s21 += __shfl_xor_sync(0xFFFFFFFFu, s21, 16);

        // redistribute: target lane<16 gathers all 4 gates of its unit
        float t10[4], t11[4], t20[4], t21[4];
        #pragma unroll
        for (int gg = 0; gg < 4; gg++){
            int src = gg * 4 + (lane & 3);
            t10[gg] = __shfl_sync(0xFFFFFFFFu, s10, src);
            t11[gg] = __shfl_sync(0xFFFFFFFFu, s11, src);
            t20[gg] = __shfl_sync(0xFFFFFFFFu, s20, src);
            t21[gg] = __shfl_sync(0xFFFFFFFFu, s21, src);
        }

        float outv = 0.f;
        if (lane < 16){
            const int L = lane >> 3;             // 0: layer1(t+1), 1: layer2(t)
            const int b = (lane >> 2) & 1;
            float p0, p1, p2, p3;
            if (L == 0){
                p0 = b ? t11[0] : t10[0];  p1 = b ? t11[1] : t10[1];
                p2 = b ? t11[2] : t10[2];  p3 = b ? t11[3] : t10[3];
            } else {
                p0 = b ? t21[0] : t20[0];  p1 = b ? t21[1] : t20[1];
                p2 = b ? t21[2] : t20[2];  p3 = b ? t21[3] : t20[3];
            }
            if (L == 1 || t < T_STEPS - 1){
                float cn = sigf(p1) * cst + sigf(p0) * tanhfast(p2);
                cst = cn;
                float h = sigf(p3) * tanhfast(cn);
                if (L == 0){
                    bcast4(&h1s[nxt][b][(int)rank * 32 + jj], h);
                } else {
                    bcast4(&h2s[nxt][b][(int)rank * 32 + jj], h);
                    outv = h;
                }
            }
        }
        __syncwarp();
        if (lane == 0) arrive4(mba);

        // hidden in the arrive->wait window: output store + x prefetch (t+2)
        if (lane >= 8 && lane < 16)
            out[((size_t)(b0 + ((lane >> 2) & 1)) * T_STEPS + t) * HID + (int)rank * 32 + jj] = outv;
        float nx0 = 0.f, nx1 = 0.f;
        if (half == 0 && t < T_STEPS - 2){
            const float* xp = g_x1 + ((size_t)(t + 2) * BATCH + b0) * GATES + grow;
            nx0 = xp[0];
            nx1 = xp[GATES];
        }

        mbar_wait_c(mba, (t + 1) & 1);
        xv0 = nx0; xv1 = nx1;
        cur = nxt;
    }
}

// ---------------------------------------------------------------------------
extern "C" void kernel_launch(void* const* d_in, const int* in_sizes, int n_in,
                              void* d_out, int out_size)
{
    (void)in_sizes; (void)n_in; (void)out_size;
    const float* feats = (const float*)d_in[0];
    const float* W_ih1 = (const float*)d_in[1];
    const float* W_hh1 = (const float*)d_in[2];
    const float* b_ih1 = (const float*)d_in[3];
    const float* b_hh1 = (const float*)d_in[4];
    const float* W_ih2 = (const float*)d_in[5];
    const float* W_hh2 = (const float*)d_in[6];
    const float* b_ih2 = (const float*)d_in[7];
    const float* b_hh2 = (const float*)d_in[8];
    float* out = (float*)d_out;

    cudaFuncSetAttribute(x1_gemm_hmma, cudaFuncAttributeMaxDynamicSharedMemorySize, GSMEM);

    dim3 g1(GATES / 128, (BATCH * T_STEPS) / 128);   // (4, 256)
    x1_gemm_hmma<<<g1, 256, GSMEM>>>(feats, W_ih1, b_ih1, b_hh1);

    lstm_rec_kernel<<<128, 256>>>(W_hh1, W_ih2, W_hh2, b_ih2, b_hh2, out);
}

// round 13
// speedup vs baseline: 1.6796x; 1.0322x over previous
#include <cuda_runtime.h>
#include <cuda_bf16.h>
#include <cstdint>

#define T_STEPS 512
#define BATCH   64
#define DIN     1024
#define HID     128
#define GATES   512   // 4*HID

// Scratch: x1[t][b][g] = feats @ W_ih1^T + b_ih1 + b_hh1   (64 MB)
__device__ float g_x1[(size_t)T_STEPS * BATCH * GATES];

// ---------------------------------------------------------------------------
// helpers
// ---------------------------------------------------------------------------
__device__ __forceinline__ uint32_t s2u(const void* p){
    uint32_t a;
    asm("{ .reg .u64 t; cvta.to.shared.u64 t, %1; cvt.u32.u64 %0, t; }" : "=r"(a) : "l"(p));
    return a;
}
__device__ __forceinline__ void ldsm4(uint32_t* r, uint32_t addr){
    asm volatile("ldmatrix.sync.aligned.m8n8.x4.shared.b16 {%0,%1,%2,%3}, [%4];"
        : "=r"(r[0]), "=r"(r[1]), "=r"(r[2]), "=r"(r[3]) : "r"(addr));
}
__device__ __forceinline__ void mma16816(float* c, const uint32_t* a, const uint32_t* b){
    asm volatile("mma.sync.aligned.m16n8k16.row.col.f32.bf16.bf16.f32 "
        "{%0,%1,%2,%3}, {%4,%5,%6,%7}, {%8,%9}, {%0,%1,%2,%3};"
        : "+f"(c[0]), "+f"(c[1]), "+f"(c[2]), "+f"(c[3])
        : "r"(a[0]), "r"(a[1]), "r"(a[2]), "r"(a[3]), "r"(b[0]), "r"(b[1]));
}
// hi bf16 pair = truncated top-16 bits of (x,y)
__device__ __forceinline__ uint2 hi_pair(float4 v){
    uint32_t x = __float_as_uint(v.x), y = __float_as_uint(v.y);
    uint32_t z = __float_as_uint(v.z), w = __float_as_uint(v.w);
    uint32_t h0, h1;
    asm("prmt.b32 %0, %1, %2, 0x7632;" : "=r"(h0) : "r"(x), "r"(y));
    asm("prmt.b32 %0, %1, %2, 0x7632;" : "=r"(h1) : "r"(z), "r"(w));
    return make_uint2(h0, h1);
}
// lo residual pair (exact subtract of truncated hi, then rn to bf16)
__device__ __forceinline__ uint2 lo_pair(float4 v){
    float lx = v.x - __uint_as_float(__float_as_uint(v.x) & 0xFFFF0000u);
    float ly = v.y - __uint_as_float(__float_as_uint(v.y) & 0xFFFF0000u);
    float lz = v.z - __uint_as_float(__float_as_uint(v.z) & 0xFFFF0000u);
    float lw = v.w - __uint_as_float(__float_as_uint(v.w) & 0xFFFF0000u);
    uint32_t l0, l1;
    asm("cvt.rn.bf16x2.f32 %0, %1, %2;" : "=r"(l0) : "f"(ly), "f"(lx));
    asm("cvt.rn.bf16x2.f32 %0, %1, %2;" : "=r"(l1) : "f"(lw), "f"(lz));
    return make_uint2(l0, l1);
}
__device__ __forceinline__ unsigned long long fma2(unsigned long long a,
        unsigned long long b, unsigned long long c){
    unsigned long long d;
    asm("fma.rn.f32x2 %0, %1, %2, %3;" : "=l"(d) : "l"(a), "l"(b), "l"(c));
    return d;
}
__device__ __forceinline__ unsigned long long packf2(float x, float y){
    unsigned long long r;
    asm("mov.b64 %0, {%1, %2};" : "=l"(r) : "f"(x), "f"(y));
    return r;
}
__device__ __forceinline__ float hsum2(unsigned long long v){
    return __uint_as_float((uint32_t)v) + __uint_as_float((uint32_t)(v >> 32));
}
__device__ __forceinline__ float sigf(float x){
    return __fdividef(1.0f, 1.0f + __expf(-x));
}
__device__ __forceinline__ float tanhfast(float x){
    return 2.0f * __fdividef(1.0f, 1.0f + __expf(-2.0f * x)) - 1.0f;
}

// ---------------------------------------------------------------------------
// Kernel 1: x1 GEMM via split-bf16 mma.sync (3 passes: hh + lh + hl).
// (unchanged — 263us, protected)
// ---------------------------------------------------------------------------
#define PITCH 80
#define TILE_B (128 * PITCH)      // 10240
#define O_AHI 0
#define O_ALO (1 * TILE_B)
#define O_BHI (2 * TILE_B)
#define O_BLO (3 * TILE_B)
#define BUFB  (4 * TILE_B)        // 40960
#define GSMEM (2 * BUFB)          // 81920

__global__ __launch_bounds__(256, 1) void x1_gemm_hmma(
    const float* __restrict__ A,
    const float* __restrict__ W,
    const float* __restrict__ bih,
    const float* __restrict__ bhh)
{
    extern __shared__ __align__(128) char smg[];
    __shared__ float biasS[128];
    const int tid  = threadIdx.x;
    const int lane = tid & 31, wid = tid >> 5;
    const int wm = wid & 3, wn = wid >> 2;
    const int m0 = blockIdx.y << 7, n0 = blockIdx.x << 7;

    if (tid < 128) biasS[tid] = bih[n0 + tid] + bhh[n0 + tid];

    const int lrow = tid >> 3;
    const int lc4  = tid & 7;
    const float* Abase = A + (size_t)(m0 + lrow) * DIN + lc4 * 4;
    const float* Wbase = W + (size_t)(n0 + lrow) * DIN + lc4 * 4;
    const int soff = lrow * PITCH + lc4 * 8;

    const uint32_t sbase = s2u(smg);
    const uint32_t a_off = (uint32_t)((wm * 32 + (lane & 15)) * PITCH + (lane >> 4) * 16);
    const uint32_t b_off = (uint32_t)((wn * 64 + (lane & 7) + 8 * (lane >> 4)) * PITCH
                                      + ((lane >> 3) & 1) * 16);

    float c[2][8][4];
    #pragma unroll
    for (int i = 0; i < 2; i++)
        #pragma unroll
        for (int j = 0; j < 8; j++)
            #pragma unroll
            for (int k = 0; k < 4; k++) c[i][j][k] = 0.f;

    float4 ra[4], rw[4];
    #pragma unroll
    for (int i = 0; i < 4; i++){
        ra[i] = *(const float4*)(Abase + (size_t)(32 * i) * DIN);
        rw[i] = *(const float4*)(Wbase + (size_t)(32 * i) * DIN);
    }
    #pragma unroll
    for (int i = 0; i < 4; i++){
        int off = soff + i * 32 * PITCH;
        *(uint2*)(smg + O_AHI + off) = hi_pair(ra[i]);
        *(uint2*)(smg + O_ALO + off) = lo_pair(ra[i]);
        *(uint2*)(smg + O_BHI + off) = hi_pair(rw[i]);
        *(uint2*)(smg + O_BLO + off) = lo_pair(rw[i]);
    }
    __syncthreads();

    for (int ci = 0; ci < 32; ci++){
        const uint32_t buf = sbase + (uint32_t)(ci & 1) * BUFB;
        if (ci < 31){
            #pragma unroll
            for (int i = 0; i < 4; i++){
                ra[i] = *(const float4*)(Abase + (size_t)(32 * i) * DIN + (ci + 1) * 32);
                rw[i] = *(const float4*)(Wbase + (size_t)(32 * i) * DIN + (ci + 1) * 32);
            }
        }
        #pragma unroll
        for (int kk = 0; kk < 2; kk++){
            uint32_t ah0[4], ah1[4], al0[4], al1[4], bh[4][4], bl[4][4];
            const uint32_t ka = a_off + kk * 32;
            const uint32_t kb = b_off + kk * 32;
            ldsm4(ah0, buf + O_AHI + ka);
            ldsm4(ah1, buf + O_AHI + ka + 16 * PITCH);
            ldsm4(al0, buf + O_ALO + ka);
            ldsm4(al1, buf + O_ALO + ka + 16 * PITCH);
            #pragma unroll
            for (int q2 = 0; q2 < 4; q2++){
                ldsm4(bh[q2], buf + O_BHI + kb + q2 * 16 * PITCH);
                ldsm4(bl[q2], buf + O_BLO + kb + q2 * 16 * PITCH);
            }
            #pragma unroll
            for (int nt = 0; nt < 8; nt++){
                const uint32_t* bhp = &bh[nt >> 1][(nt & 1) * 2];
                const uint32_t* blp = &bl[nt >> 1][(nt & 1) * 2];
                mma16816(c[0][nt], ah0, bhp);
                mma16816(c[1][nt], ah1, bhp);
                mma16816(c[0][nt], al0, bhp);
                mma16816(c[1][nt], al1, bhp);
                mma16816(c[0][nt], ah0, blp);
                mma16816(c[1][nt], ah1, blp);
            }
        }
        if (ci < 31){
            char* b = smg + ((ci + 1) & 1) * BUFB;
            #pragma unroll
            for (int i = 0; i < 4; i++){
                int off = soff + i * 32 * PITCH;
                *(uint2*)(b + O_AHI + off) = hi_pair(ra[i]);
                *(uint2*)(b + O_ALO + off) = lo_pair(ra[i]);
                *(uint2*)(b + O_BHI + off) = hi_pair(rw[i]);
                *(uint2*)(b + O_BLO + off) = lo_pair(rw[i]);
            }
        }
        __syncthreads();
    }

    const int gr = lane >> 2;
    const int gc = (lane & 3) * 2;
    #pragma unroll
    for (int mt = 0; mt < 2; mt++){
        #pragma unroll
        for (int nt = 0; nt < 8; nt++){
            const int n = wn * 64 + nt * 8 + gc;
            const float b0 = biasS[n], b1 = biasS[n + 1];
            #pragma unroll
            for (int rr = 0; rr < 2; rr++){
                const int m = m0 + wm * 32 + mt * 16 + gr + rr * 8;
                const int bb = m >> 9;
                const int tt = m & 511;
                float2 o = make_float2(c[mt][nt][rr * 2 + 0] + b0,
                                       c[mt][nt][rr * 2 + 1] + b1);
                *(float2*)(g_x1 + ((size_t)tt * BATCH + bb) * GATES + n0 + n) = o;
            }
        }
    }
}

// ---------------------------------------------------------------------------
// Kernel 2: recurrence. 32 clusters x 4 CTAs, 2 batches/cluster.
// CHANGE vs round 12: per-CTA arrive aggregation. __syncthreads() collects
// all 8 warps (and orders their DSMEM stores), then ONE thread issues the 4
// remote mbarrier arrives. Barrier count 32 -> 4: removes ~28 serialized
// smem-atomic arrive ops (~700-900 cyc) per barrier per step.
// ---------------------------------------------------------------------------
__device__ __forceinline__ void bcast4(const float* addr, float v){
    uint32_t la = (uint32_t)__cvta_generic_to_shared(addr);
    #pragma unroll
    for (int pr = 0; pr < 4; pr++){
        uint32_t raddr;
        asm volatile("mapa.shared::cluster.u32 %0, %1, %2;" : "=r"(raddr) : "r"(la), "r"(pr));
        asm volatile("st.shared::cluster.f32 [%0], %1;" :: "r"(raddr), "f"(v) : "memory");
    }
}
__device__ __forceinline__ void arrive4(uint32_t la){
    #pragma unroll
    for (int pr = 0; pr < 4; pr++){
        uint32_t raddr;
        asm volatile("mapa.shared::cluster.u32 %0, %1, %2;" : "=r"(raddr) : "r"(la), "r"(pr));
        asm volatile("mbarrier.arrive.shared::cluster.b64 _, [%0];" :: "r"(raddr) : "memory");
    }
}
__device__ __forceinline__ void mbar_wait_c(uint32_t mb, uint32_t parity){
    asm volatile(
        "{\n\t.reg .pred P;\n\t"
        "WL_%=:\n\t"
        "mbarrier.try_wait.parity.acquire.cluster.shared::cta.b64 P, [%0], %1;\n\t"
        "@!P bra WL_%=;\n\t"
        "}\n" :: "r"(mb), "r"(parity) : "memory");
}

__global__ void __cluster_dims__(4,1,1) __launch_bounds__(256, 1)
lstm_rec_kernel(const float* __restrict__ Whh1,
                const float* __restrict__ Wih2,
                const float* __restrict__ Whh2,
                const float* __restrict__ bih2,
                const float* __restrict__ bhh2,
                float* __restrict__ out)
{
    __shared__ __align__(16) float h1s[2][2][HID];
    __shared__ __align__(16) float h2s[2][2][HID];
    __shared__ __align__(8) unsigned long long mbar;

    const int tid  = threadIdx.x;
    const int w    = tid >> 5;
    const int lane = tid & 31;
    const int half = lane >> 4;         // k-half
    const int u    = lane & 15;
    const int g    = u >> 2;            // gate 0..3
    const int jo   = u & 3;
    const int jj   = w * 4 + jo;        // j within this CTA's 32-slice
    uint32_t rank;
    asm("mov.u32 %0, %%cluster_ctarank;" : "=r"(rank));
    const int b0   = (blockIdx.x >> 2) * 2;
    const int grow = g * 128 + (int)rank * 32 + jj;
    const uint32_t mba = (uint32_t)__cvta_generic_to_shared(&mbar);

    // register-resident packed weight slices (96 b64 = 192 regs)
    unsigned long long w1p[32], w2p[32], w3p[32];
    {
        const float4* p1 = (const float4*)(Whh1 + (size_t)grow * HID + half * 64);
        const float4* p2 = (const float4*)(Wih2 + (size_t)grow * HID + half * 64);
        const float4* p3 = (const float4*)(Whh2 + (size_t)grow * HID + half * 64);
        #pragma unroll
        for (int k = 0; k < 16; k++){
            float4 v1 = p1[k], v2 = p2[k], v3 = p3[k];
            w1p[2*k]   = packf2(v1.x, v1.y);  w1p[2*k+1] = packf2(v1.z, v1.w);
            w2p[2*k]   = packf2(v2.x, v2.y);  w2p[2*k+1] = packf2(v2.z, v2.w);
            w3p[2*k]   = packf2(v3.x, v3.y);  w3p[2*k+1] = packf2(v3.z, v3.w);
        }
    }
    const float b2v = bih2[grow] + bhh2[grow];

    for (int i = tid; i < 2*2*HID; i += 256){
        (&h1s[0][0][0])[i] = 0.f;
        (&h2s[0][0][0])[i] = 0.f;
    }
    if (tid == 0){
        asm volatile("mbarrier.init.shared.b64 [%0], %1;" :: "r"(mba), "r"(4u) : "memory");
    }
    __syncthreads();
    asm volatile("barrier.cluster.arrive.aligned;" ::: "memory");
    asm volatile("barrier.cluster.wait.aligned;"   ::: "memory");

    // Prologue: layer1(t=0) from x only. Gate-unit lanes 0-7 own c1, 8-15 own c2.
    float cst = 0.f;
    if (lane < 8){
        const int b = (lane >> 2) & 1;
        const float* xp = g_x1 + ((size_t)0 * BATCH + b0 + b) * GATES + (int)rank * 32 + jj;
        float p0 = xp[0], p2 = xp[256], p3 = xp[384];
        cst = sigf(p0) * tanhfast(p2);
        float h = sigf(p3) * tanhfast(cst);
        bcast4(&h1s[0][b][(int)rank * 32 + jj], h);
    }
    float xv0 = 0.f, xv1 = 0.f;
    if (half == 0){
        const float* xp = g_x1 + ((size_t)1 * BATCH + b0) * GATES + grow;
        xv0 = xp[0];
        xv1 = xp[GATES];
    }
    __syncthreads();
    if (tid == 0) arrive4(mba);
    mbar_wait_c(mba, 0);

    int cur = 0;
    for (int t = 0; t < T_STEPS; t++){
        const int nxt = cur ^ 1;

        // packed dot products: LDS.128 yields two f32x2 operands directly
        const ulonglong2* A0 = (const ulonglong2*)&h1s[cur][0][half * 64];
        const ulonglong2* A1 = (const ulonglong2*)&h1s[cur][1][half * 64];
        const ulonglong2* D0 = (const ulonglong2*)&h2s[cur][0][half * 64];
        const ulonglong2* D1 = (const ulonglong2*)&h2s[cur][1][half * 64];
        unsigned long long q10 = 0ull, q11 = 0ull;
        unsigned long long q20 = 0ull, q21 = 0ull, r20 = 0ull, r21 = 0ull;
        #pragma unroll
        for (int k4 = 0; k4 < 16; k4++){
            ulonglong2 a0 = A0[k4], a1 = A1[k4], d0 = D0[k4], d1 = D1[k4];
            q10 = fma2(w1p[2*k4], a0.x, q10);  q10 = fma2(w1p[2*k4+1], a0.y, q10);
            q11 = fma2(w1p[2*k4], a1.x, q11);  q11 = fma2(w1p[2*k4+1], a1.y, q11);
            q20 = fma2(w2p[2*k4], a0.x, q20);  q20 = fma2(w2p[2*k4+1], a0.y, q20);
            q21 = fma2(w2p[2*k4], a1.x, q21);  q21 = fma2(w2p[2*k4+1], a1.y, q21);
            r20 = fma2(w3p[2*k4], d0.x, r20);  r20 = fma2(w3p[2*k4+1], d0.y, r20);
            r21 = fma2(w3p[2*k4], d1.x, r21);  r21 = fma2(w3p[2*k4+1], d1.y, r21);
        }
        float s10 = hsum2(q10) + xv0;
        float s11 = hsum2(q11) + xv1;
        float s20 = hsum2(q20) + hsum2(r20) + (half ? 0.f : b2v);
        float s21 = hsum2(q21) + hsum2(r21) + (half ? 0.f : b2v);
        s10 += __shfl_xor_sync(0xFFFFFFFFu, s10, 16);
        s11 += __shfl_xor_sync(0xFFFFFFFFu, s11, 16);
        s20 += __shfl_xor_sync(0xFFFFFFFFu, s20, 16);
        s21 += __shfl_xor_sync(0xFFFFFFFFu, s21, 16);

        // redistribute: target lane<16 gathers all 4 gates of its unit
        float t10[4], t11[4], t20[4], t21[4];
        #pragma unroll
        for (int gg = 0; gg < 4; gg++){
            int src = gg * 4 + (lane & 3);
            t10[gg] = __shfl_sync(0xFFFFFFFFu, s10, src);
            t11[gg] = __shfl_sync(0xFFFFFFFFu, s11, src);
            t20[gg] = __shfl_sync(0xFFFFFFFFu, s20, src);
            t21[gg] = __shfl_sync(0xFFFFFFFFu, s21, src);
        }

        float outv = 0.f;
        if (lane < 16){
            const int L = lane >> 3;             // 0: layer1(t+1), 1: layer2(t)
            const int b = (lane >> 2) & 1;
            float p0, p1, p2, p3;
            if (L == 0){
                p0 = b ? t11[0] : t10[0];  p1 = b ? t11[1] : t10[1];
                p2 = b ? t11[2] : t10[2];  p3 = b ? t11[3] : t10[3];
            } else {
                p0 = b ? t21[0] : t20[0];  p1 = b ? t21[1] : t20[1];
                p2 = b ? t21[2] : t20[2];  p3 = b ? t21[3] : t20[3];
            }
            if (L == 1 || t < T_STEPS - 1){
                float cn = sigf(p1) * cst + sigf(p0) * tanhfast(p2);
                cst = cn;
                float h = sigf(p3) * tanhfast(cn);
                if (L == 0){
                    bcast4(&h1s[nxt][b][(int)rank * 32 + jj], h);
                } else {
                    bcast4(&h2s[nxt][b][(int)rank * 32 + jj], h);
                    outv = h;
                }
            }
        }

        // overlap with the sync window: output store + x prefetch for t+2
        if (lane >= 8 && lane < 16)
            out[((size_t)(b0 + ((lane >> 2) & 1)) * T_STEPS + t) * HID + (int)rank * 32 + jj] = outv;
        float nx0 = 0.f, nx1 = 0.f;
        if (half == 0 && t < T_STEPS - 2){
            const float* xp = g_x1 + ((size_t)(t + 2) * BATCH + b0) * GATES + grow;
            nx0 = xp[0];
            nx1 = xp[GATES];
        }

        // per-CTA aggregation: one local BAR, then a single remote arrive fan-out
        __syncthreads();
        if (tid == 0) arrive4(mba);
        mbar_wait_c(mba, (t + 1) & 1);
        xv0 = nx0; xv1 = nx1;
        cur = nxt;
    }
}

// ---------------------------------------------------------------------------
extern "C" void kernel_launch(void* const* d_in, const int* in_sizes, int n_in,
                              void* d_out, int out_size)
{
    (void)in_sizes; (void)n_in; (void)out_size;
    const float* feats = (const float*)d_in[0];
    const float* W_ih1 = (const float*)d_in[1];
    const float* W_hh1 = (const float*)d_in[2];
    const float* b_ih1 = (const float*)d_in[3];
    const float* b_hh1 = (const float*)d_in[4];
    const float* W_ih2 = (const float*)d_in[5];
    const float* W_hh2 = (const float*)d_in[6];
    const float* b_ih2 = (const float*)d_in[7];
    const float* b_hh2 = (const float*)d_in[8];
    float* out = (float*)d_out;

    cudaFuncSetAttribute(x1_gemm_hmma, cudaFuncAttributeMaxDynamicSharedMemorySize, GSMEM);

    dim3 g1(GATES / 128, (BATCH * T_STEPS) / 128);   // (4, 256)
    x1_gemm_hmma<<<g1, 256, GSMEM>>>(feats, W_ih1, b_ih1, b_hh1);

    lstm_rec_kernel<<<128, 256>>>(W_hh1, W_ih2, W_hh2, b_ih2, b_hh2, out);
}

// round 15
// speedup vs baseline: 1.7598x; 1.0478x over previous
#include <cuda_runtime.h>
#include <cuda_bf16.h>
#include <cstdint>

#define T_STEPS 512
#define BATCH   64
#define DIN     1024
#define HID     128
#define GATES   512   // 4*HID

// Scratch: x1[t][b][g] = feats @ W_ih1^T + b_ih1 + b_hh1   (64 MB)
__device__ float g_x1[(size_t)T_STEPS * BATCH * GATES];

// ---------------------------------------------------------------------------
// helpers
// ---------------------------------------------------------------------------
__device__ __forceinline__ uint32_t s2u(const void* p){
    uint32_t a;
    asm("{ .reg .u64 t; cvta.to.shared.u64 t, %1; cvt.u32.u64 %0, t; }" : "=r"(a) : "l"(p));
    return a;
}
__device__ __forceinline__ void ldsm4(uint32_t* r, uint32_t addr){
    asm volatile("ldmatrix.sync.aligned.m8n8.x4.shared.b16 {%0,%1,%2,%3}, [%4];"
        : "=r"(r[0]), "=r"(r[1]), "=r"(r[2]), "=r"(r[3]) : "r"(addr));
}
__device__ __forceinline__ void mma16816(float* c, const uint32_t* a, const uint32_t* b){
    asm volatile("mma.sync.aligned.m16n8k16.row.col.f32.bf16.bf16.f32 "
        "{%0,%1,%2,%3}, {%4,%5,%6,%7}, {%8,%9}, {%0,%1,%2,%3};"
        : "+f"(c[0]), "+f"(c[1]), "+f"(c[2]), "+f"(c[3])
        : "r"(a[0]), "r"(a[1]), "r"(a[2]), "r"(a[3]), "r"(b[0]), "r"(b[1]));
}
// hi bf16 pair = truncated top-16 bits of (x,y)
__device__ __forceinline__ uint2 hi_pair(float4 v){
    uint32_t x = __float_as_uint(v.x), y = __float_as_uint(v.y);
    uint32_t z = __float_as_uint(v.z), w = __float_as_uint(v.w);
    uint32_t h0, h1;
    asm("prmt.b32 %0, %1, %2, 0x7632;" : "=r"(h0) : "r"(x), "r"(y));
    asm("prmt.b32 %0, %1, %2, 0x7632;" : "=r"(h1) : "r"(z), "r"(w));
    return make_uint2(h0, h1);
}
// lo residual pair (exact subtract of truncated hi, then rn to bf16)
__device__ __forceinline__ uint2 lo_pair(float4 v){
    float lx = v.x - __uint_as_float(__float_as_uint(v.x) & 0xFFFF0000u);
    float ly = v.y - __uint_as_float(__float_as_uint(v.y) & 0xFFFF0000u);
    float lz = v.z - __uint_as_float(__float_as_uint(v.z) & 0xFFFF0000u);
    float lw = v.w - __uint_as_float(__float_as_uint(v.w) & 0xFFFF0000u);
    uint32_t l0, l1;
    asm("cvt.rn.bf16x2.f32 %0, %1, %2;" : "=r"(l0) : "f"(ly), "f"(lx));
    asm("cvt.rn.bf16x2.f32 %0, %1, %2;" : "=r"(l1) : "f"(lw), "f"(lz));
    return make_uint2(l0, l1);
}
__device__ __forceinline__ unsigned long long fma2(unsigned long long a,
        unsigned long long b, unsigned long long c){
    unsigned long long d;
    asm("fma.rn.f32x2 %0, %1, %2, %3;" : "=l"(d) : "l"(a), "l"(b), "l"(c));
    return d;
}
__device__ __forceinline__ unsigned long long packf2(float x, float y){
    unsigned long long r;
    asm("mov.b64 %0, {%1, %2};" : "=l"(r) : "f"(x), "f"(y));
    return r;
}
__device__ __forceinline__ float hsum2(unsigned long long v){
    return __uint_as_float((uint32_t)v) + __uint_as_float((uint32_t)(v >> 32));
}
__device__ __forceinline__ float sigf(float x){
    return __fdividef(1.0f, 1.0f + __expf(-x));
}
__device__ __forceinline__ float tanhfast(float x){
    return 2.0f * __fdividef(1.0f, 1.0f + __expf(-2.0f * x)) - 1.0f;
}

// ---------------------------------------------------------------------------
// Kernel 1: x1 GEMM via split-bf16 mma.sync (3 passes: hh + lh + hl).
// (unchanged — 263us, protected)
// ---------------------------------------------------------------------------
#define PITCH 80
#define TILE_B (128 * PITCH)      // 10240
#define O_AHI 0
#define O_ALO (1 * TILE_B)
#define O_BHI (2 * TILE_B)
#define O_BLO (3 * TILE_B)
#define BUFB  (4 * TILE_B)        // 40960
#define GSMEM (2 * BUFB)          // 81920

__global__ __launch_bounds__(256, 1) void x1_gemm_hmma(
    const float* __restrict__ A,
    const float* __restrict__ W,
    const float* __restrict__ bih,
    const float* __restrict__ bhh)
{
    extern __shared__ __align__(128) char smg[];
    __shared__ float biasS[128];
    const int tid  = threadIdx.x;
    const int lane = tid & 31, wid = tid >> 5;
    const int wm = wid & 3, wn = wid >> 2;
    const int m0 = blockIdx.y << 7, n0 = blockIdx.x << 7;

    if (tid < 128) biasS[tid] = bih[n0 + tid] + bhh[n0 + tid];

    const int lrow = tid >> 3;
    const int lc4  = tid & 7;
    const float* Abase = A + (size_t)(m0 + lrow) * DIN + lc4 * 4;
    const float* Wbase = W + (size_t)(n0 + lrow) * DIN + lc4 * 4;
    const int soff = lrow * PITCH + lc4 * 8;

    const uint32_t sbase = s2u(smg);
    const uint32_t a_off = (uint32_t)((wm * 32 + (lane & 15)) * PITCH + (lane >> 4) * 16);
    const uint32_t b_off = (uint32_t)((wn * 64 + (lane & 7) + 8 * (lane >> 4)) * PITCH
                                      + ((lane >> 3) & 1) * 16);

    float c[2][8][4];
    #pragma unroll
    for (int i = 0; i < 2; i++)
        #pragma unroll
        for (int j = 0; j < 8; j++)
            #pragma unroll
            for (int k = 0; k < 4; k++) c[i][j][k] = 0.f;

    float4 ra[4], rw[4];
    #pragma unroll
    for (int i = 0; i < 4; i++){
        ra[i] = *(const float4*)(Abase + (size_t)(32 * i) * DIN);
        rw[i] = *(const float4*)(Wbase + (size_t)(32 * i) * DIN);
    }
    #pragma unroll
    for (int i = 0; i < 4; i++){
        int off = soff + i * 32 * PITCH;
        *(uint2*)(smg + O_AHI + off) = hi_pair(ra[i]);
        *(uint2*)(smg + O_ALO + off) = lo_pair(ra[i]);
        *(uint2*)(smg + O_BHI + off) = hi_pair(rw[i]);
        *(uint2*)(smg + O_BLO + off) = lo_pair(rw[i]);
    }
    __syncthreads();

    for (int ci = 0; ci < 32; ci++){
        const uint32_t buf = sbase + (uint32_t)(ci & 1) * BUFB;
        if (ci < 31){
            #pragma unroll
            for (int i = 0; i < 4; i++){
                ra[i] = *(const float4*)(Abase + (size_t)(32 * i) * DIN + (ci + 1) * 32);
                rw[i] = *(const float4*)(Wbase + (size_t)(32 * i) * DIN + (ci + 1) * 32);
            }
        }
        #pragma unroll
        for (int kk = 0; kk < 2; kk++){
            uint32_t ah0[4], ah1[4], al0[4], al1[4], bh[4][4], bl[4][4];
            const uint32_t ka = a_off + kk * 32;
            const uint32_t kb = b_off + kk * 32;
            ldsm4(ah0, buf + O_AHI + ka);
            ldsm4(ah1, buf + O_AHI + ka + 16 * PITCH);
            ldsm4(al0, buf + O_ALO + ka);
            ldsm4(al1, buf + O_ALO + ka + 16 * PITCH);
            #pragma unroll
            for (int q2 = 0; q2 < 4; q2++){
                ldsm4(bh[q2], buf + O_BHI + kb + q2 * 16 * PITCH);
                ldsm4(bl[q2], buf + O_BLO + kb + q2 * 16 * PITCH);
            }
            #pragma unroll
            for (int nt = 0; nt < 8; nt++){
                const uint32_t* bhp = &bh[nt >> 1][(nt & 1) * 2];
                const uint32_t* blp = &bl[nt >> 1][(nt & 1) * 2];
                mma16816(c[0][nt], ah0, bhp);
                mma16816(c[1][nt], ah1, bhp);
                mma16816(c[0][nt], al0, bhp);
                mma16816(c[1][nt], al1, bhp);
                mma16816(c[0][nt], ah0, blp);
                mma16816(c[1][nt], ah1, blp);
            }
        }
        if (ci < 31){
            char* b = smg + ((ci + 1) & 1) * BUFB;
            #pragma unroll
            for (int i = 0; i < 4; i++){
                int off = soff + i * 32 * PITCH;
                *(uint2*)(b + O_AHI + off) = hi_pair(ra[i]);
                *(uint2*)(b + O_ALO + off) = lo_pair(ra[i]);
                *(uint2*)(b + O_BHI + off) = hi_pair(rw[i]);
                *(uint2*)(b + O_BLO + off) = lo_pair(rw[i]);
            }
        }
        __syncthreads();
    }

    const int gr = lane >> 2;
    const int gc = (lane & 3) * 2;
    #pragma unroll
    for (int mt = 0; mt < 2; mt++){
        #pragma unroll
        for (int nt = 0; nt < 8; nt++){
            const int n = wn * 64 + nt * 8 + gc;
            const float b0 = biasS[n], b1 = biasS[n + 1];
            #pragma unroll
            for (int rr = 0; rr < 2; rr++){
                const int m = m0 + wm * 32 + mt * 16 + gr + rr * 8;
                const int bb = m >> 9;
                const int tt = m & 511;
                float2 o = make_float2(c[mt][nt][rr * 2 + 0] + b0,
                                       c[mt][nt][rr * 2 + 1] + b1);
                *(float2*)(g_x1 + ((size_t)tt * BATCH + bb) * GATES + n0 + n) = o;
            }
        }
    }
}

// ---------------------------------------------------------------------------
// Kernel 2: recurrence, k-split-4 layout. 32 clusters x 4 CTAs, 2 batches.
// lane = (slot<<2) | c : c = k-chunk (32 floats), slot: jl = slot&3,
// gate-pair = slot>>2. Each thread: 6 rows (3 matrices x 2 gates) x 32 k
// x 2 batches = 192 fma2, but only 32 LDS.128 (vs 64 in the half-split).
// h stored in 36-float-padded chunks (conflict-free 4-address LDS).
// Quad shfl reduction + one xor(16) gate-pair exchange.
// ---------------------------------------------------------------------------
__device__ __forceinline__ void bcast4(const float* addr, float v){
    uint32_t la = (uint32_t)__cvta_generic_to_shared(addr);
    #pragma unroll
    for (int pr = 0; pr < 4; pr++){
        uint32_t raddr;
        asm volatile("mapa.shared::cluster.u32 %0, %1, %2;" : "=r"(raddr) : "r"(la), "r"(pr));
        asm volatile("st.shared::cluster.f32 [%0], %1;" :: "r"(raddr), "f"(v) : "memory");
    }
}
__device__ __forceinline__ void arrive4(uint32_t la){
    #pragma unroll
    for (int pr = 0; pr < 4; pr++){
        uint32_t raddr;
        asm volatile("mapa.shared::cluster.u32 %0, %1, %2;" : "=r"(raddr) : "r"(la), "r"(pr));
        asm volatile("mbarrier.arrive.shared::cluster.b64 _, [%0];" :: "r"(raddr) : "memory");
    }
}
__device__ __forceinline__ void mbar_wait_c(uint32_t mb, uint32_t parity){
    asm volatile(
        "{\n\t.reg .pred P;\n\t"
        "WL_%=:\n\t"
        "mbarrier.try_wait.parity.acquire.cluster.shared::cta.b64 P, [%0], %1;\n\t"
        "@!P bra WL_%=;\n\t"
        "}\n" :: "r"(mb), "r"(parity) : "memory");
}

#define HPAD 36   // padded chunk stride (floats); 4 chunks = 144

__global__ void __cluster_dims__(4,1,1) __launch_bounds__(256, 1)
lstm_rec_kernel(const float* __restrict__ Whh1,
                const float* __restrict__ Wih2,
                const float* __restrict__ Whh2,
                const float* __restrict__ bih2,
                const float* __restrict__ bhh2,
                float* __restrict__ out)
{
    __shared__ __align__(16) float h1s[2][2][4 * HPAD];
    __shared__ __align__(16) float h2s[2][2][4 * HPAD];
    __shared__ __align__(8) unsigned long long mbar;

    const int tid  = threadIdx.x;
    const int w    = tid >> 5;
    const int lane = tid & 31;
    const int c    = lane & 3;          // k-chunk: [32c, 32c+32)
    const int slot = lane >> 2;         // 0..7
    const int jl   = slot & 3;
    const int gp   = slot >> 2;         // gate pair: gates {2gp, 2gp+1}
    const int Lu   = (lane >> 1) & 1;   // gate-unit layer (lane<16)
    const int bu   = lane & 1;          // gate-unit batch
    uint32_t rank;
    asm("mov.u32 %0, %%cluster_ctarank;" : "=r"(rank));
    const int b0     = (blockIdx.x >> 2) * 2;
    const int j_cta  = w * 4 + jl;                 // 0..31 within CTA slice
    const int j_glob = (int)rank * 32 + j_cta;
    const uint32_t mba = (uint32_t)__cvta_generic_to_shared(&mbar);

    // register-resident packed weights: [gate-in-pair][k-pair], 96 b64 total
    unsigned long long w1p[2][16], w2p[2][16], w3p[2][16];
    #pragma unroll
    for (int gg = 0; gg < 2; gg++){
        const int row = (2 * gp + gg) * 128 + j_glob;
        const float4* p1 = (const float4*)(Whh1 + (size_t)row * HID + c * 32);
        const float4* p2 = (const float4*)(Wih2 + (size_t)row * HID + c * 32);
        const float4* p3 = (const float4*)(Whh2 + (size_t)row * HID + c * 32);
        #pragma unroll
        for (int q = 0; q < 8; q++){
            float4 v1 = p1[q], v2 = p2[q], v3 = p3[q];
            w1p[gg][2*q] = packf2(v1.x, v1.y);  w1p[gg][2*q+1] = packf2(v1.z, v1.w);
            w2p[gg][2*q] = packf2(v2.x, v2.y);  w2p[gg][2*q+1] = packf2(v2.z, v2.w);
            w3p[gg][2*q] = packf2(v3.x, v3.y);  w3p[gg][2*q+1] = packf2(v3.z, v3.w);
        }
    }

    // gate-unit constants (lane<16): layer-2 units need 4 bias values
    float b2r0 = 0.f, b2r1 = 0.f, b2r2 = 0.f, b2r3 = 0.f;
    if (lane < 16 && Lu == 1){
        b2r0 = bih2[0 * 128 + j_glob] + bhh2[0 * 128 + j_glob];
        b2r1 = bih2[1 * 128 + j_glob] + bhh2[1 * 128 + j_glob];
        b2r2 = bih2[2 * 128 + j_glob] + bhh2[2 * 128 + j_glob];
        b2r3 = bih2[3 * 128 + j_glob] + bhh2[3 * 128 + j_glob];
    }

    for (int i = tid; i < 2 * 2 * 4 * HPAD; i += 256){
        (&h1s[0][0][0])[i] = 0.f;
        (&h2s[0][0][0])[i] = 0.f;
    }
    if (tid == 0){
        asm volatile("mbarrier.init.shared.b64 [%0], %1;" :: "r"(mba), "r"(4u) : "memory");
    }
    __syncthreads();
    asm volatile("barrier.cluster.arrive.aligned;" ::: "memory");
    asm volatile("barrier.cluster.wait.aligned;"   ::: "memory");

    // Prologue: h1(0) from x(0) only; load x(1) for step 0's layer-1 gates.
    float cst = 0.f;
    float xu0 = 0.f, xu1 = 0.f, xu2 = 0.f, xu3 = 0.f;
    if (lane < 16 && Lu == 0){
        const float* xp = g_x1 + ((size_t)0 * BATCH + b0 + bu) * GATES + j_glob;
        float p0 = xp[0], p2 = xp[256], p3 = xp[384];
        cst = sigf(p0) * tanhfast(p2);
        float h = sigf(p3) * tanhfast(cst);
        bcast4(&h1s[0][bu][(int)rank * HPAD + j_cta], h);
        const float* xq = g_x1 + ((size_t)1 * BATCH + b0 + bu) * GATES + j_glob;
        xu0 = xq[0]; xu1 = xq[128]; xu2 = xq[256]; xu3 = xq[384];
    }
    __syncthreads();
    if (tid == 0) arrive4(mba);
    mbar_wait_c(mba, 0);

    int cur = 0;
    for (int t = 0; t < T_STEPS; t++){
        const int nxt = cur ^ 1;

        // prefetch x(t+2) early so it overlaps the FMA window
        float xn0 = 0.f, xn1 = 0.f, xn2 = 0.f, xn3 = 0.f;
        if (lane < 16 && Lu == 0 && t < T_STEPS - 2){
            const float* xq = g_x1 + ((size_t)(t + 2) * BATCH + b0 + bu) * GATES + j_glob;
            xn0 = xq[0]; xn1 = xq[128]; xn2 = xq[256]; xn3 = xq[384];
        }

        // dot products: 32 LDS.128, 192 fma2
        const ulonglong2* A0 = (const ulonglong2*)&h1s[cur][0][c * HPAD];
        const ulonglong2* A1 = (const ulonglong2*)&h1s[cur][1][c * HPAD];
        const ulonglong2* D0 = (const ulonglong2*)&h2s[cur][0][c * HPAD];
        const ulonglong2* D1 = (const ulonglong2*)&h2s[cur][1][c * HPAD];
        unsigned long long a1[2][2] = {{0ull,0ull},{0ull,0ull}};
        unsigned long long a2[2][2] = {{0ull,0ull},{0ull,0ull}};
        unsigned long long a3[2][2] = {{0ull,0ull},{0ull,0ull}};
        #pragma unroll
        for (int i = 0; i < 8; i++){
            ulonglong2 av0 = A0[i], av1 = A1[i], dv0 = D0[i], dv1 = D1[i];
            #pragma unroll
            for (int gg = 0; gg < 2; gg++){
                a1[gg][0] = fma2(w1p[gg][2*i], av0.x, a1[gg][0]);
                a1[gg][0] = fma2(w1p[gg][2*i+1], av0.y, a1[gg][0]);
                a1[gg][1] = fma2(w1p[gg][2*i], av1.x, a1[gg][1]);
                a1[gg][1] = fma2(w1p[gg][2*i+1], av1.y, a1[gg][1]);
                a2[gg][0] = fma2(w2p[gg][2*i], av0.x, a2[gg][0]);
                a2[gg][0] = fma2(w2p[gg][2*i+1], av0.y, a2[gg][0]);
                a2[gg][1] = fma2(w2p[gg][2*i], av1.x, a2[gg][1]);
                a2[gg][1] = fma2(w2p[gg][2*i+1], av1.y, a2[gg][1]);
                a3[gg][0] = fma2(w3p[gg][2*i], dv0.x, a3[gg][0]);
                a3[gg][0] = fma2(w3p[gg][2*i+1], dv0.y, a3[gg][0]);
                a3[gg][1] = fma2(w3p[gg][2*i], dv1.x, a3[gg][1]);
                a3[gg][1] = fma2(w3p[gg][2*i+1], dv1.y, a3[gg][1]);
            }
        }
        float S1[2][2], S23[2][2];
        #pragma unroll
        for (int gg = 0; gg < 2; gg++){
            #pragma unroll
            for (int b = 0; b < 2; b++){
                S1[gg][b]  = hsum2(a1[gg][b]);
                S23[gg][b] = hsum2(a2[gg][b]) + hsum2(a3[gg][b]);
            }
        }
        // quad reduction across the 4 k-chunks (lanes c=0..3 of each slot)
        #pragma unroll
        for (int gg = 0; gg < 2; gg++){
            #pragma unroll
            for (int b = 0; b < 2; b++){
                S1[gg][b]  += __shfl_xor_sync(0xFFFFFFFFu, S1[gg][b],  1);
                S1[gg][b]  += __shfl_xor_sync(0xFFFFFFFFu, S1[gg][b],  2);
                S23[gg][b] += __shfl_xor_sync(0xFFFFFFFFu, S23[gg][b], 1);
                S23[gg][b] += __shfl_xor_sync(0xFFFFFFFFu, S23[gg][b], 2);
            }
        }
        // gate-pair exchange: lane selects its (layer, batch), swaps with slot^4
        float v0 = Lu ? S23[0][bu] : S1[0][bu];   // gate 2gp+0
        float v1 = Lu ? S23[1][bu] : S1[1][bu];   // gate 2gp+1
        float v2 = __shfl_xor_sync(0xFFFFFFFFu, v0, 16);  // partner's pair
        float v3 = __shfl_xor_sync(0xFFFFFFFFu, v1, 16);

        float outv = 0.f;
        int dow = 0;
        if (lane < 16){
            if (Lu == 0){
                if (t < T_STEPS - 1){
                    float p0 = v0 + xu0, p1 = v1 + xu1, p2 = v2 + xu2, p3 = v3 + xu3;
                    float cn = sigf(p1) * cst + sigf(p0) * tanhfast(p2);
                    cst = cn;
                    float h = sigf(p3) * tanhfast(cn);
                    bcast4(&h1s[nxt][bu][(int)rank * HPAD + j_cta], h);
                }
            } else {
                float p0 = v0 + b2r0, p1 = v1 + b2r1, p2 = v2 + b2r2, p3 = v3 + b2r3;
                float cn = sigf(p1) * cst + sigf(p0) * tanhfast(p2);
                cst = cn;
                float h = sigf(p3) * tanhfast(cn);
                bcast4(&h2s[nxt][bu][(int)rank * HPAD + j_cta], h);
                outv = h; dow = 1;
            }
        }
        if (dow)
            out[((size_t)(b0 + bu) * T_STEPS + t) * HID + j_glob] = outv;
        xu0 = xn0; xu1 = xn1; xu2 = xn2; xu3 = xn3;

        // per-CTA aggregation: local BAR orders DSMEM stores, single arrive fan-out
        __syncthreads();
        if (tid == 0) arrive4(mba);
        mbar_wait_c(mba, (t + 1) & 1);
        cur = nxt;
    }
}

// ---------------------------------------------------------------------------
extern "C" void kernel_launch(void* const* d_in, const int* in_sizes, int n_in,
                              void* d_out, int out_size)
{
    (void)in_sizes; (void)n_in; (void)out_size;
    const float* feats = (const float*)d_in[0];
    const float* W_ih1 = (const float*)d_in[1];
    const float* W_hh1 = (const float*)d_in[2];
    const float* b_ih1 = (const float*)d_in[3];
    const float* b_hh1 = (const float*)d_in[4];
    const float* W_ih2 = (const float*)d_in[5];
    const float* W_hh2 = (const float*)d_in[6];
    const float* b_ih2 = (const float*)d_in[7];
    const float* b_hh2 = (const float*)d_in[8];
    float* out = (float*)d_out;

    cudaFuncSetAttribute(x1_gemm_hmma, cudaFuncAttributeMaxDynamicSharedMemorySize, GSMEM);

    dim3 g1(GATES / 128, (BATCH * T_STEPS) / 128);   // (4, 256)
    x1_gemm_hmma<<<g1, 256, GSMEM>>>(feats, W_ih1, b_ih1, b_hh1);

    lstm_rec_kernel<<<128, 256>>>(W_hh1, W_ih2, W_hh2, b_ih2, b_hh2, out);
}

// round 16
// speedup vs baseline: 1.7763x; 1.0094x over previous
#include <cuda_runtime.h>
#include <cuda_bf16.h>
#include <cstdint>

#define T_STEPS 512
#define BATCH   64
#define DIN     1024
#define HID     128
#define GATES   512   // 4*HID

// Scratch: x1[t][b][g] = feats @ W_ih1^T + b_ih1 + b_hh1   (64 MB)
__device__ float g_x1[(size_t)T_STEPS * BATCH * GATES];

// ---------------------------------------------------------------------------
// helpers
// ---------------------------------------------------------------------------
__device__ __forceinline__ uint32_t s2u(const void* p){
    uint32_t a;
    asm("{ .reg .u64 t; cvta.to.shared.u64 t, %1; cvt.u32.u64 %0, t; }" : "=r"(a) : "l"(p));
    return a;
}
__device__ __forceinline__ void ldsm4(uint32_t* r, uint32_t addr){
    asm volatile("ldmatrix.sync.aligned.m8n8.x4.shared.b16 {%0,%1,%2,%3}, [%4];"
        : "=r"(r[0]), "=r"(r[1]), "=r"(r[2]), "=r"(r[3]) : "r"(addr));
}
__device__ __forceinline__ void mma16816(float* c, const uint32_t* a, const uint32_t* b){
    asm volatile("mma.sync.aligned.m16n8k16.row.col.f32.bf16.bf16.f32 "
        "{%0,%1,%2,%3}, {%4,%5,%6,%7}, {%8,%9}, {%0,%1,%2,%3};"
        : "+f"(c[0]), "+f"(c[1]), "+f"(c[2]), "+f"(c[3])
        : "r"(a[0]), "r"(a[1]), "r"(a[2]), "r"(a[3]), "r"(b[0]), "r"(b[1]));
}
// hi bf16 pair = truncated top-16 bits of (x,y)
__device__ __forceinline__ uint2 hi_pair(float4 v){
    uint32_t x = __float_as_uint(v.x), y = __float_as_uint(v.y);
    uint32_t z = __float_as_uint(v.z), w = __float_as_uint(v.w);
    uint32_t h0, h1;
    asm("prmt.b32 %0, %1, %2, 0x7632;" : "=r"(h0) : "r"(x), "r"(y));
    asm("prmt.b32 %0, %1, %2, 0x7632;" : "=r"(h1) : "r"(z), "r"(w));
    return make_uint2(h0, h1);
}
// lo residual pair (exact subtract of truncated hi, then rn to bf16)
__device__ __forceinline__ uint2 lo_pair(float4 v){
    float lx = v.x - __uint_as_float(__float_as_uint(v.x) & 0xFFFF0000u);
    float ly = v.y - __uint_as_float(__float_as_uint(v.y) & 0xFFFF0000u);
    float lz = v.z - __uint_as_float(__float_as_uint(v.z) & 0xFFFF0000u);
    float lw = v.w - __uint_as_float(__float_as_uint(v.w) & 0xFFFF0000u);
    uint32_t l0, l1;
    asm("cvt.rn.bf16x2.f32 %0, %1, %2;" : "=r"(l0) : "f"(ly), "f"(lx));
    asm("cvt.rn.bf16x2.f32 %0, %1, %2;" : "=r"(l1) : "f"(lw), "f"(lz));
    return make_uint2(l0, l1);
}
__device__ __forceinline__ unsigned long long fma2(unsigned long long a,
        unsigned long long b, unsigned long long c){
    unsigned long long d;
    asm("fma.rn.f32x2 %0, %1, %2, %3;" : "=l"(d) : "l"(a), "l"(b), "l"(c));
    return d;
}
__device__ __forceinline__ unsigned long long packf2(float x, float y){
    unsigned long long r;
    asm("mov.b64 %0, {%1, %2};" : "=l"(r) : "f"(x), "f"(y));
    return r;
}
__device__ __forceinline__ float hsum2(unsigned long long v){
    return __uint_as_float((uint32_t)v) + __uint_as_float((uint32_t)(v >> 32));
}
__device__ __forceinline__ float sigf(float x){
    return __fdividef(1.0f, 1.0f + __expf(-x));
}
__device__ __forceinline__ float tanhfast(float x){
    return 2.0f * __fdividef(1.0f, 1.0f + __expf(-2.0f * x)) - 1.0f;
}

// ---------------------------------------------------------------------------
// Kernel 1: x1 GEMM via split-bf16 mma.sync (3 passes: hh + lh + hl).
// (unchanged — 263us, protected)
// ---------------------------------------------------------------------------
#define PITCH 80
#define TILE_B (128 * PITCH)      // 10240
#define O_AHI 0
#define O_ALO (1 * TILE_B)
#define O_BHI (2 * TILE_B)
#define O_BLO (3 * TILE_B)
#define BUFB  (4 * TILE_B)        // 40960
#define GSMEM (2 * BUFB)          // 81920

__global__ __launch_bounds__(256, 1) void x1_gemm_hmma(
    const float* __restrict__ A,
    const float* __restrict__ W,
    const float* __restrict__ bih,
    const float* __restrict__ bhh)
{
    extern __shared__ __align__(128) char smg[];
    __shared__ float biasS[128];
    const int tid  = threadIdx.x;
    const int lane = tid & 31, wid = tid >> 5;
    const int wm = wid & 3, wn = wid >> 2;
    const int m0 = blockIdx.y << 7, n0 = blockIdx.x << 7;

    if (tid < 128) biasS[tid] = bih[n0 + tid] + bhh[n0 + tid];

    const int lrow = tid >> 3;
    const int lc4  = tid & 7;
    const float* Abase = A + (size_t)(m0 + lrow) * DIN + lc4 * 4;
    const float* Wbase = W + (size_t)(n0 + lrow) * DIN + lc4 * 4;
    const int soff = lrow * PITCH + lc4 * 8;

    const uint32_t sbase = s2u(smg);
    const uint32_t a_off = (uint32_t)((wm * 32 + (lane & 15)) * PITCH + (lane >> 4) * 16);
    const uint32_t b_off = (uint32_t)((wn * 64 + (lane & 7) + 8 * (lane >> 4)) * PITCH
                                      + ((lane >> 3) & 1) * 16);

    float c[2][8][4];
    #pragma unroll
    for (int i = 0; i < 2; i++)
        #pragma unroll
        for (int j = 0; j < 8; j++)
            #pragma unroll
            for (int k = 0; k < 4; k++) c[i][j][k] = 0.f;

    float4 ra[4], rw[4];
    #pragma unroll
    for (int i = 0; i < 4; i++){
        ra[i] = *(const float4*)(Abase + (size_t)(32 * i) * DIN);
        rw[i] = *(const float4*)(Wbase + (size_t)(32 * i) * DIN);
    }
    #pragma unroll
    for (int i = 0; i < 4; i++){
        int off = soff + i * 32 * PITCH;
        *(uint2*)(smg + O_AHI + off) = hi_pair(ra[i]);
        *(uint2*)(smg + O_ALO + off) = lo_pair(ra[i]);
        *(uint2*)(smg + O_BHI + off) = hi_pair(rw[i]);
        *(uint2*)(smg + O_BLO + off) = lo_pair(rw[i]);
    }
    __syncthreads();

    for (int ci = 0; ci < 32; ci++){
        const uint32_t buf = sbase + (uint32_t)(ci & 1) * BUFB;
        if (ci < 31){
            #pragma unroll
            for (int i = 0; i < 4; i++){
                ra[i] = *(const float4*)(Abase + (size_t)(32 * i) * DIN + (ci + 1) * 32);
                rw[i] = *(const float4*)(Wbase + (size_t)(32 * i) * DIN + (ci + 1) * 32);
            }
        }
        #pragma unroll
        for (int kk = 0; kk < 2; kk++){
            uint32_t ah0[4], ah1[4], al0[4], al1[4], bh[4][4], bl[4][4];
            const uint32_t ka = a_off + kk * 32;
            const uint32_t kb = b_off + kk * 32;
            ldsm4(ah0, buf + O_AHI + ka);
            ldsm4(ah1, buf + O_AHI + ka + 16 * PITCH);
            ldsm4(al0, buf + O_ALO + ka);
            ldsm4(al1, buf + O_ALO + ka + 16 * PITCH);
            #pragma unroll
            for (int q2 = 0; q2 < 4; q2++){
                ldsm4(bh[q2], buf + O_BHI + kb + q2 * 16 * PITCH);
                ldsm4(bl[q2], buf + O_BLO + kb + q2 * 16 * PITCH);
            }
            #pragma unroll
            for (int nt = 0; nt < 8; nt++){
                const uint32_t* bhp = &bh[nt >> 1][(nt & 1) * 2];
                const uint32_t* blp = &bl[nt >> 1][(nt & 1) * 2];
                mma16816(c[0][nt], ah0, bhp);
                mma16816(c[1][nt], ah1, bhp);
                mma16816(c[0][nt], al0, bhp);
                mma16816(c[1][nt], al1, bhp);
                mma16816(c[0][nt], ah0, blp);
                mma16816(c[1][nt], ah1, blp);
            }
        }
        if (ci < 31){
            char* b = smg + ((ci + 1) & 1) * BUFB;
            #pragma unroll
            for (int i = 0; i < 4; i++){
                int off = soff + i * 32 * PITCH;
                *(uint2*)(b + O_AHI + off) = hi_pair(ra[i]);
                *(uint2*)(b + O_ALO + off) = lo_pair(ra[i]);
                *(uint2*)(b + O_BHI + off) = hi_pair(rw[i]);
                *(uint2*)(b + O_BLO + off) = lo_pair(rw[i]);
            }
        }
        __syncthreads();
    }

    const int gr = lane >> 2;
    const int gc = (lane & 3) * 2;
    #pragma unroll
    for (int mt = 0; mt < 2; mt++){
        #pragma unroll
        for (int nt = 0; nt < 8; nt++){
            const int n = wn * 64 + nt * 8 + gc;
            const float b0 = biasS[n], b1 = biasS[n + 1];
            #pragma unroll
            for (int rr = 0; rr < 2; rr++){
                const int m = m0 + wm * 32 + mt * 16 + gr + rr * 8;
                const int bb = m >> 9;
                const int tt = m & 511;
                float2 o = make_float2(c[mt][nt][rr * 2 + 0] + b0,
                                       c[mt][nt][rr * 2 + 1] + b1);
                *(float2*)(g_x1 + ((size_t)tt * BATCH + bb) * GATES + n0 + n) = o;
            }
        }
    }
}

// ---------------------------------------------------------------------------
// Kernel 2: recurrence, k-split-4 layout (r15) + st.async tx-barrier sync.
// Gate units push h via st.async.shared::cluster.mbarrier::complete_tx —
// store data AND barrier credit travel in one fabric hop. No __syncthreads,
// no arrive fan-out. Two mbarriers (even/odd step), expect_tx = 2048 B/step
// (4 source CTAs x 128 floats), re-armed by tid0 right after each wait.
// ---------------------------------------------------------------------------
__device__ __forceinline__ void stasync4(const float* addr, float v,
                                         const unsigned long long* mb){
    uint32_t la = (uint32_t)__cvta_generic_to_shared(addr);
    uint32_t lb = (uint32_t)__cvta_generic_to_shared(mb);
    uint32_t vi = __float_as_uint(v);
    #pragma unroll
    for (int pr = 0; pr < 4; pr++){
        uint32_t ra, rb;
        asm volatile("mapa.shared::cluster.u32 %0, %1, %2;" : "=r"(ra) : "r"(la), "r"(pr));
        asm volatile("mapa.shared::cluster.u32 %0, %1, %2;" : "=r"(rb) : "r"(lb), "r"(pr));
        asm volatile("st.async.shared::cluster.mbarrier::complete_tx::bytes.b32 [%0], %1, [%2];"
                     :: "r"(ra), "r"(vi), "r"(rb) : "memory");
    }
}
__device__ __forceinline__ void mbar_expect(uint32_t mb, uint32_t tx){
    asm volatile("mbarrier.arrive.expect_tx.shared.b64 _, [%0], %1;"
                 :: "r"(mb), "r"(tx) : "memory");
}
__device__ __forceinline__ void mbar_wait_c(uint32_t mb, uint32_t parity){
    asm volatile(
        "{\n\t.reg .pred P;\n\t"
        "WL_%=:\n\t"
        "mbarrier.try_wait.parity.acquire.cluster.shared::cta.b64 P, [%0], %1;\n\t"
        "@!P bra WL_%=;\n\t"
        "}\n" :: "r"(mb), "r"(parity) : "memory");
}

#define HPAD 36   // padded chunk stride (floats); 4 chunks = 144

__global__ void __cluster_dims__(4,1,1) __launch_bounds__(256, 1)
lstm_rec_kernel(const float* __restrict__ Whh1,
                const float* __restrict__ Wih2,
                const float* __restrict__ Whh2,
                const float* __restrict__ bih2,
                const float* __restrict__ bhh2,
                float* __restrict__ out)
{
    __shared__ __align__(16) float h1s[2][2][4 * HPAD];
    __shared__ __align__(16) float h2s[2][2][4 * HPAD];
    __shared__ __align__(16) unsigned long long mbar[2];

    const int tid  = threadIdx.x;
    const int w    = tid >> 5;
    const int lane = tid & 31;
    const int c    = lane & 3;          // k-chunk: [32c, 32c+32)
    const int slot = lane >> 2;         // 0..7
    const int jl   = slot & 3;
    const int gp   = slot >> 2;         // gate pair: gates {2gp, 2gp+1}
    const int Lu   = (lane >> 1) & 1;   // gate-unit layer (lane<16)
    const int bu   = lane & 1;          // gate-unit batch
    uint32_t rank;
    asm("mov.u32 %0, %%cluster_ctarank;" : "=r"(rank));
    const int b0     = (blockIdx.x >> 2) * 2;
    const int j_cta  = w * 4 + jl;                 // 0..31 within CTA slice
    const int j_glob = (int)rank * 32 + j_cta;
    const uint32_t mba = (uint32_t)__cvta_generic_to_shared(&mbar[0]);

    // register-resident packed weights: [gate-in-pair][k-pair], 96 b64 total
    unsigned long long w1p[2][16], w2p[2][16], w3p[2][16];
    #pragma unroll
    for (int gg = 0; gg < 2; gg++){
        const int row = (2 * gp + gg) * 128 + j_glob;
        const float4* p1 = (const float4*)(Whh1 + (size_t)row * HID + c * 32);
        const float4* p2 = (const float4*)(Wih2 + (size_t)row * HID + c * 32);
        const float4* p3 = (const float4*)(Whh2 + (size_t)row * HID + c * 32);
        #pragma unroll
        for (int q = 0; q < 8; q++){
            float4 v1 = p1[q], v2 = p2[q], v3 = p3[q];
            w1p[gg][2*q] = packf2(v1.x, v1.y);  w1p[gg][2*q+1] = packf2(v1.z, v1.w);
            w2p[gg][2*q] = packf2(v2.x, v2.y);  w2p[gg][2*q+1] = packf2(v2.z, v2.w);
            w3p[gg][2*q] = packf2(v3.x, v3.y);  w3p[gg][2*q+1] = packf2(v3.z, v3.w);
        }
    }

    // gate-unit constants (lane<16): layer-2 units need 4 bias values
    float b2r0 = 0.f, b2r1 = 0.f, b2r2 = 0.f, b2r3 = 0.f;
    if (lane < 16 && Lu == 1){
        b2r0 = bih2[0 * 128 + j_glob] + bhh2[0 * 128 + j_glob];
        b2r1 = bih2[1 * 128 + j_glob] + bhh2[1 * 128 + j_glob];
        b2r2 = bih2[2 * 128 + j_glob] + bhh2[2 * 128 + j_glob];
        b2r3 = bih2[3 * 128 + j_glob] + bhh2[3 * 128 + j_glob];
    }

    for (int i = tid; i < 2 * 2 * 4 * HPAD; i += 256){
        (&h1s[0][0][0])[i] = 0.f;
        (&h2s[0][0][0])[i] = 0.f;
    }
    if (tid == 0){
        asm volatile("mbarrier.init.shared.b64 [%0], %1;" :: "r"(mba), "r"(1u) : "memory");
        asm volatile("mbarrier.init.shared.b64 [%0], %1;" :: "r"(mba + 8), "r"(1u) : "memory");
        mbar_expect(mba,     1024u);   // prologue: h1(0) only
        mbar_expect(mba + 8, 2048u);   // step 0 stores h(1)
    }
    __syncthreads();
    asm volatile("barrier.cluster.arrive.aligned;" ::: "memory");
    asm volatile("barrier.cluster.wait.aligned;"   ::: "memory");

    // Prologue: h1(0) from x(0) only; load x(1) for step 0's layer-1 gates.
    float cst = 0.f;
    float xu0 = 0.f, xu1 = 0.f, xu2 = 0.f, xu3 = 0.f;
    if (lane < 16 && Lu == 0){
        const float* xp = g_x1 + ((size_t)0 * BATCH + b0 + bu) * GATES + j_glob;
        float p0 = xp[0], p2 = xp[256], p3 = xp[384];
        cst = sigf(p0) * tanhfast(p2);
        float h = sigf(p3) * tanhfast(cst);
        stasync4(&h1s[0][bu][(int)rank * HPAD + j_cta], h, &mbar[0]);
        const float* xq = g_x1 + ((size_t)1 * BATCH + b0 + bu) * GATES + j_glob;
        xu0 = xq[0]; xu1 = xq[128]; xu2 = xq[256]; xu3 = xq[384];
    }
    mbar_wait_c(mba, 0);
    if (tid == 0) mbar_expect(mba, 2048u);   // re-arm for step 1

    int cur = 0;
    for (int t = 0; t < T_STEPS; t++){
        const int nxt = cur ^ 1;
        const int b   = (t + 1) & 1;                 // barrier fed this step
        const uint32_t mbt = mba + (uint32_t)(b << 3);

        // prefetch x(t+2) early so it overlaps the FMA window
        float xn0 = 0.f, xn1 = 0.f, xn2 = 0.f, xn3 = 0.f;
        if (lane < 16 && Lu == 0 && t < T_STEPS - 2){
            const float* xq = g_x1 + ((size_t)(t + 2) * BATCH + b0 + bu) * GATES + j_glob;
            xn0 = xq[0]; xn1 = xq[128]; xn2 = xq[256]; xn3 = xq[384];
        }

        // dot products: 32 LDS.128, 192 fma2
        const ulonglong2* A0 = (const ulonglong2*)&h1s[cur][0][c * HPAD];
        const ulonglong2* A1 = (const ulonglong2*)&h1s[cur][1][c * HPAD];
        const ulonglong2* D0 = (const ulonglong2*)&h2s[cur][0][c * HPAD];
        const ulonglong2* D1 = (const ulonglong2*)&h2s[cur][1][c * HPAD];
        unsigned long long a1[2][2] = {{0ull,0ull},{0ull,0ull}};
        unsigned long long a2[2][2] = {{0ull,0ull},{0ull,0ull}};
        unsigned long long a3[2][2] = {{0ull,0ull},{0ull,0ull}};
        #pragma unroll
        for (int i = 0; i < 8; i++){
            ulonglong2 av0 = A0[i], av1 = A1[i], dv0 = D0[i], dv1 = D1[i];
            #pragma unroll
            for (int gg = 0; gg < 2; gg++){
                a1[gg][0] = fma2(w1p[gg][2*i], av0.x, a1[gg][0]);
                a1[gg][0] = fma2(w1p[gg][2*i+1], av0.y, a1[gg][0]);
                a1[gg][1] = fma2(w1p[gg][2*i], av1.x, a1[gg][1]);
                a1[gg][1] = fma2(w1p[gg][2*i+1], av1.y, a1[gg][1]);
                a2[gg][0] = fma2(w2p[gg][2*i], av0.x, a2[gg][0]);
                a2[gg][0] = fma2(w2p[gg][2*i+1], av0.y, a2[gg][0]);
                a2[gg][1] = fma2(w2p[gg][2*i], av1.x, a2[gg][1]);
                a2[gg][1] = fma2(w2p[gg][2*i+1], av1.y, a2[gg][1]);
                a3[gg][0] = fma2(w3p[gg][2*i], dv0.x, a3[gg][0]);
                a3[gg][0] = fma2(w3p[gg][2*i+1], dv0.y, a3[gg][0]);
                a3[gg][1] = fma2(w3p[gg][2*i], dv1.x, a3[gg][1]);
                a3[gg][1] = fma2(w3p[gg][2*i+1], dv1.y, a3[gg][1]);
            }
        }
        float S1[2][2], S23[2][2];
        #pragma unroll
        for (int gg = 0; gg < 2; gg++){
            #pragma unroll
            for (int bb = 0; bb < 2; bb++){
                S1[gg][bb]  = hsum2(a1[gg][bb]);
                S23[gg][bb] = hsum2(a2[gg][bb]) + hsum2(a3[gg][bb]);
            }
        }
        // quad reduction across the 4 k-chunks
        #pragma unroll
        for (int gg = 0; gg < 2; gg++){
            #pragma unroll
            for (int bb = 0; bb < 2; bb++){
                S1[gg][bb]  += __shfl_xor_sync(0xFFFFFFFFu, S1[gg][bb],  1);
                S1[gg][bb]  += __shfl_xor_sync(0xFFFFFFFFu, S1[gg][bb],  2);
                S23[gg][bb] += __shfl_xor_sync(0xFFFFFFFFu, S23[gg][bb], 1);
                S23[gg][bb] += __shfl_xor_sync(0xFFFFFFFFu, S23[gg][bb], 2);
            }
        }
        // gate-pair exchange: lane selects its (layer, batch), swaps with slot^4
        float v0 = Lu ? S23[0][bu] : S1[0][bu];   // gate 2gp+0
        float v1 = Lu ? S23[1][bu] : S1[1][bu];   // gate 2gp+1
        float v2 = __shfl_xor_sync(0xFFFFFFFFu, v0, 16);
        float v3 = __shfl_xor_sync(0xFFFFFFFFu, v1, 16);

        float outv = 0.f;
        int dow = 0;
        if (lane < 16){
            if (Lu == 0){
                // always compute+store (keeps tx count uniform; t=T-1 value unused)
                float p0 = v0 + xu0, p1 = v1 + xu1, p2 = v2 + xu2, p3 = v3 + xu3;
                float cn = sigf(p1) * cst + sigf(p0) * tanhfast(p2);
                cst = cn;
                float h = sigf(p3) * tanhfast(cn);
                stasync4(&h1s[nxt][bu][(int)rank * HPAD + j_cta], h, &mbar[b]);
            } else {
                float p0 = v0 + b2r0, p1 = v1 + b2r1, p2 = v2 + b2r2, p3 = v3 + b2r3;
                float cn = sigf(p1) * cst + sigf(p0) * tanhfast(p2);
                cst = cn;
                float h = sigf(p3) * tanhfast(cn);
                stasync4(&h2s[nxt][bu][(int)rank * HPAD + j_cta], h, &mbar[b]);
                outv = h; dow = 1;
            }
        }
        if (dow)
            out[((size_t)(b0 + bu) * T_STEPS + t) * HID + j_glob] = outv;
        xu0 = xn0; xu1 = xn1; xu2 = xn2; xu3 = xn3;

        // wait for all 4 CTAs' h(t+1) tx; re-arm for the barrier's next use (t+2)
        int par = (t >> 1) & 1;
        if (!b) par ^= 1;
        mbar_wait_c(mbt, (uint32_t)par);
        if (tid == 0) mbar_expect(mbt, 2048u);
        cur = nxt;
    }
}

// ---------------------------------------------------------------------------
extern "C" void kernel_launch(void* const* d_in, const int* in_sizes, int n_in,
                              void* d_out, int out_size)
{
    (void)in_sizes; (void)n_in; (void)out_size;
    const float* feats = (const float*)d_in[0];
    const float* W_ih1 = (const float*)d_in[1];
    const float* W_hh1 = (const float*)d_in[2];
    const float* b_ih1 = (const float*)d_in[3];
    const float* b_hh1 = (const float*)d_in[4];
    const float* W_ih2 = (const float*)d_in[5];
    const float* W_hh2 = (const float*)d_in[6];
    const float* b_ih2 = (const float*)d_in[7];
    const float* b_hh2 = (const float*)d_in[8];
    float* out = (float*)d_out;

    cudaFuncSetAttribute(x1_gemm_hmma, cudaFuncAttributeMaxDynamicSharedMemorySize, GSMEM);

    dim3 g1(GATES / 128, (BATCH * T_STEPS) / 128);   // (4, 256)
    x1_gemm_hmma<<<g1, 256, GSMEM>>>(feats, W_ih1, b_ih1, b_hh1);

    lstm_rec_kernel<<<128, 256>>>(W_hh1, W_ih2, W_hh2, b_ih2, b_hh2, out);
}